// round 12
// baseline (speedup 1.0000x reference)
#include <cuda_runtime.h>
#include <cuda_fp16.h>
#include <math.h>
#include <stdint.h>

// ---------------------------------------------------------------------------
// REGC hetero-GNN. Types [author 200000, fos 30000, inst 5000, paper 150000].
// 7 relations x 400000 edges. L1: 128->256 (H=8,NB=4,DH=32) mean+max.
// L2: 256->349 mean. fp16 HMMA GEMMs (register-prefetch mainloop, packed fp16
// weights, BM=128 BN=128); CSR aggregation; fp16 intermediates.
// ---------------------------------------------------------------------------

#define E     400000
#define RTOT  885000
#define TOTE  2800000
#define NPAD  384

__device__ __half g_xh   [(size_t)385000 * 128];
__device__ __half g_bases[(size_t)385000 * 128];
__device__ __half g_out1 [(size_t)385000 * 256];   // post-ReLU
__device__ __half g_wroot[(size_t)385000 * 32];
__device__ __half g_wrel [(size_t)RTOT * 64];
__device__ __half g_sum2 [(size_t)RTOT * 256];
__device__ __half g_w1p  [4][(size_t)128 * NPAD];
__device__ float  g_b1p  [4][NPAD];
__device__ __half g_w2p  [4][(size_t)1024 * NPAD];
__device__ int    g_cnt   [RTOT];
__device__ int    g_rowptr[RTOT + 1];
__device__ int    g_cursor[RTOT];
__device__ int    g_ebuf  [TOTE];
__device__ int    g_bsum  [512];

__device__ __constant__ int c_ST[7]   = {0, 2, 0, 3, 3, 3, 1};
__device__ __constant__ int c_OFF[4]  = {0, 200000, 230000, 235000};
__device__ __constant__ int c_ROFF[7] = {0, 5000, 205000, 355000, 555000, 705000, 735000};

// ---------------------------------------------------------------------------
// fp16 GEMM, register-prefetch mainloop, BM=128 BN=128 BK=32, 256 threads.
// Warps: 4 (M) x 2 (N); warp tile 32x64. A re-read per N-tile halved vs BN=64.
// A: up to 4 fp16 row-segments, aStride halves/row. B: packed [nit*32][NPAD].
// mode 0: C f32 = acc + bias (L2 logits, row stride 349, scalar stores)
// mode 1: scatter cols [0,128)->g_bases, [128,160)->g_wroot, [160,..)->g_wrel
// ---------------------------------------------------------------------------
__global__ void __launch_bounds__(256) hgemm_h(
    const __half* A0, const __half* A1, const __half* A2, const __half* A3,
    const __half* __restrict__ Bp, const float* __restrict__ bias,
    float* __restrict__ Cf,
    int M, int aStride, int segShift, int nit, int mode,
    int nodeOff, int ro0, int ro1, int ro2, int Ncols)
{
    __shared__ __align__(16) __half As[128][40];
    __shared__ __align__(16) __half Bs[32][136];

    const __half* Aseg[4] = {A0, A1, A2, A3};
    const int tid  = threadIdx.x;
    const int lane = tid & 31;
    const int warp = tid >> 5;
    const int wm = (warp & 3) * 32;
    const int wn = (warp >> 2) * 64;
    const int m0 = blockIdx.y * 128;
    const int n0 = blockIdx.x * 128;

    // A: 128 rows x 32 halves; thread -> (row, 16-half chunk)
    const int am = tid >> 1;
    const int ak = (tid & 1) * 16;
    // B: 32 rows x 128 halves = 512 16B chunks; 2 per thread
    const int bq0 = tid * 2;
    const int bk0 = bq0 >> 4,       bn0 = (bq0 & 15) * 8;
    const int bk1 = (bq0 + 1) >> 4, bn1 = ((bq0 + 1) & 15) * 8;

    uint4 pa0, pa1, pb0, pb1;

    auto load_g = [&](int it) {
        const int seg = it >> segShift;
        const int k0 = (it - (seg << segShift)) * 32;
        const int gm = m0 + am;
        const __half* ap = Aseg[seg] + (size_t)(gm < M ? gm : 0) * aStride + k0 + ak;
        pa0 = *(const uint4*)ap;
        pa1 = *(const uint4*)(ap + 8);
        pb0 = *(const uint4*)(Bp + (size_t)(it * 32 + bk0) * NPAD + n0 + bn0);
        pb1 = *(const uint4*)(Bp + (size_t)(it * 32 + bk1) * NPAD + n0 + bn1);
    };
    auto store_s = [&]() {
        *(uint4*)&As[am][ak]     = pa0;
        *(uint4*)&As[am][ak + 8] = pa1;
        *(uint4*)&Bs[bk0][bn0]   = pb0;
        *(uint4*)&Bs[bk1][bn1]   = pb1;
    };

    float acc[2][8][4];
#pragma unroll
    for (int mi = 0; mi < 2; mi++)
#pragma unroll
        for (int nj = 0; nj < 8; nj++)
#pragma unroll
            for (int r = 0; r < 4; r++) acc[mi][nj][r] = 0.f;

    const uint32_t sA = (uint32_t)__cvta_generic_to_shared(&As[0][0]);
    const uint32_t sB = (uint32_t)__cvta_generic_to_shared(&Bs[0][0]);
    const uint32_t aAddr0 = sA + (uint32_t)((wm + (lane & 15)) * 80 + ((lane >> 4) * 8) * 2);
    const uint32_t bAddr0 = sB + (uint32_t)(((lane & 15)) * 272 + (wn + (lane >> 4) * 8) * 2);

    auto compute = [&]() {
#pragma unroll
        for (int kk = 0; kk < 2; kk++) {
            uint32_t a[2][4], b[8][2];
#pragma unroll
            for (int mi = 0; mi < 2; mi++) {
                uint32_t addr = aAddr0 + (uint32_t)(mi * 16 * 80 + kk * 16 * 2);
                asm volatile("ldmatrix.sync.aligned.m8n8.x4.shared.b16 {%0,%1,%2,%3}, [%4];"
                             : "=r"(a[mi][0]), "=r"(a[mi][1]), "=r"(a[mi][2]), "=r"(a[mi][3])
                             : "r"(addr));
            }
#pragma unroll
            for (int njp = 0; njp < 4; njp++) {
                uint32_t addr = bAddr0 + (uint32_t)(kk * 16 * 272 + njp * 16 * 2);
                asm volatile("ldmatrix.sync.aligned.m8n8.x4.trans.shared.b16 {%0,%1,%2,%3}, [%4];"
                             : "=r"(b[njp * 2][0]), "=r"(b[njp * 2][1]),
                               "=r"(b[njp * 2 + 1][0]), "=r"(b[njp * 2 + 1][1])
                             : "r"(addr));
            }
#pragma unroll
            for (int mi = 0; mi < 2; mi++)
#pragma unroll
                for (int nj = 0; nj < 8; nj++) {
                    asm volatile(
                        "mma.sync.aligned.m16n8k16.row.col.f32.f16.f16.f32 "
                        "{%0,%1,%2,%3}, {%4,%5,%6,%7}, {%8,%9}, {%0,%1,%2,%3};"
                        : "+f"(acc[mi][nj][0]), "+f"(acc[mi][nj][1]),
                          "+f"(acc[mi][nj][2]), "+f"(acc[mi][nj][3])
                        : "r"(a[mi][0]), "r"(a[mi][1]), "r"(a[mi][2]), "r"(a[mi][3]),
                          "r"(b[nj][0]), "r"(b[nj][1]));
                }
        }
    };

    load_g(0);
    store_s();
    __syncthreads();
    for (int it = 1; it < nit; it++) {
        load_g(it);
        compute();
        __syncthreads();
        store_s();
        __syncthreads();
    }
    compute();

    // ---- epilogue ----
#pragma unroll
    for (int mi = 0; mi < 2; mi++)
#pragma unroll
        for (int nj = 0; nj < 8; nj++)
#pragma unroll
            for (int rp = 0; rp < 2; rp++) {
                const int row = m0 + wm + mi * 16 + (lane >> 2) + rp * 8;
                const int col = n0 + wn + nj * 8 + (lane & 3) * 2;
                if (row >= M || col >= Ncols) continue;
                const bool pair = (col + 1 < Ncols);
                const float v0 = acc[mi][nj][rp * 2 + 0] + bias[col];
                const float v1 = acc[mi][nj][rp * 2 + 1] + bias[pair ? col + 1 : col];
                if (mode == 0) {
                    // 349-stride rows: only 4B alignment guaranteed -> scalar
                    float* p = Cf + (size_t)row * 349 + col;
                    p[0] = v0;
                    if (pair) p[1] = v1;
                } else {
                    const __half2 h2 = __floats2half2_rn(v0, v1);
                    if (col < 128) {
                        *(__half2*)(g_bases + (size_t)(nodeOff + row) * 128 + col) = h2;
                    } else if (col < 160) {
                        *(__half2*)(g_wroot + (size_t)(nodeOff + row) * 32 + (col - 128)) = h2;
                    } else {
                        const int cc = col - 160;
                        const int rr = cc >> 6;
                        const int ro = (rr == 0) ? ro0 : ((rr == 1) ? ro1 : ro2);
                        *(__half2*)(g_wrel + (size_t)(ro + row) * 64 + (cc & 63)) = h2;
                    }
                }
            }
}

// ---------------------------------------------------------------------------
// prep kernels (validated R8/R11)
// ---------------------------------------------------------------------------
__global__ void cvt_half(const float* __restrict__ x, __half* __restrict__ y, int n)
{
    const int i = blockIdx.x * blockDim.x + threadIdx.x;
    if (i < n) y[i] = __float2half_rn(x[i]);
}

__global__ void pack_w1(const float* __restrict__ bases_w1,
                        const float* __restrict__ root_w1,
                        const float* __restrict__ rel_w1,
                        const float* __restrict__ root_b1,
                        const float* __restrict__ rel_b1,
                        __half* __restrict__ w1p, float* __restrict__ b1p,
                        int t, int R, int e0, int e1, int e2)
{
    const int i = blockIdx.x * blockDim.x + threadIdx.x;
    if (i >= 128 * NPAD) return;
    const int k = i / NPAD, n = i % NPAD;
    float v = 0.f, b = 0.f;
    if (n < 128) {
        v = bases_w1[k * 128 + n];
    } else if (n < 160) {
        v = root_w1[((size_t)t * 32 + (n - 128)) * 128 + k];
        b = root_b1[t * 32 + (n - 128)];
    } else {
        const int cc = n - 160;
        const int r = cc >> 6;
        if (r < R) {
            const int e = (r == 0) ? e0 : ((r == 1) ? e1 : e2);
            v = rel_w1[((size_t)e * 64 + (cc & 63)) * 128 + k];
            b = rel_b1[e * 64 + (cc & 63)];
        }
    }
    w1p[(size_t)k * NPAD + n] = __float2half_rn(v);
    if (k == 0) b1p[n] = b;
}

__global__ void pack_w2(const float* __restrict__ root_w2,
                        const float* __restrict__ rel_w2,
                        __half* __restrict__ w2p,
                        int t, int nseg, int e1, int e2, int e3)
{
    const int i = blockIdx.x * blockDim.x + threadIdx.x;
    if (i >= nseg * 256 * NPAD) return;
    const int kg = i / NPAD, n = i % NPAD;
    const int seg = kg >> 8, k = kg & 255;
    float v = 0.f;
    if (n < 349) {
        if (seg == 0) v = root_w2[((size_t)t * 349 + n) * 256 + k];
        else {
            const int e = (seg == 1) ? e1 : ((seg == 2) ? e2 : e3);
            v = rel_w2[((size_t)e * 349 + n) * 256 + k];
        }
    }
    w2p[(size_t)kg * NPAD + n] = __float2half_rn(v);
}

// ---------------------------------------------------------------------------
// CSR build (validated R5-R11)
// ---------------------------------------------------------------------------
__global__ void count_kernel(const int* __restrict__ dst_idx)
{
    const int e = blockIdx.y;
    const int i = blockIdx.x * blockDim.x + threadIdx.x;
    if (i >= E) return;
    atomicAdd(&g_cnt[c_ROFF[e] + dst_idx[(size_t)e * E + i]], 1);
}

__global__ void __launch_bounds__(256) scan1_kernel()
{
    __shared__ int s[256];
    const int tid = threadIdx.x;
    const int tbase = blockIdx.x * 2048 + tid * 8;
    int vals[8];
    int tsum = 0;
#pragma unroll
    for (int j = 0; j < 8; j++) {
        int v = (tbase + j < RTOT) ? g_cnt[tbase + j] : 0;
        vals[j] = tsum;
        tsum += v;
    }
    s[tid] = tsum;
    __syncthreads();
    for (int off = 1; off < 256; off <<= 1) {
        int t = (tid >= off) ? s[tid - off] : 0;
        __syncthreads();
        s[tid] += t;
        __syncthreads();
    }
    const int texcl = (tid > 0) ? s[tid - 1] : 0;
    if (tid == 255) g_bsum[blockIdx.x] = s[255];
#pragma unroll
    for (int j = 0; j < 8; j++)
        if (tbase + j < RTOT) g_rowptr[tbase + j] = vals[j] + texcl;
}

__global__ void __launch_bounds__(512) scan2_kernel(int nb)
{
    __shared__ int s[512];
    const int tid = threadIdx.x;
    s[tid] = (tid < nb) ? g_bsum[tid] : 0;
    __syncthreads();
    for (int off = 1; off < 512; off <<= 1) {
        int t = (tid >= off) ? s[tid - off] : 0;
        __syncthreads();
        s[tid] += t;
        __syncthreads();
    }
    g_bsum[tid] = (tid > 0) ? s[tid - 1] : 0;
}

__global__ void scan3_kernel()
{
    const int i = blockIdx.x * blockDim.x + threadIdx.x;
    if (i < RTOT) {
        int v = g_rowptr[i] + g_bsum[i >> 11];
        g_rowptr[i] = v;
        g_cursor[i] = v;
    } else if (i == RTOT) {
        g_rowptr[RTOT] = TOTE;
    }
}

__global__ void fill_kernel(const int* __restrict__ src_idx,
                            const int* __restrict__ dst_idx)
{
    const int e = blockIdx.y;
    const int i = blockIdx.x * blockDim.x + threadIdx.x;
    if (i >= E) return;
    const int d = dst_idx[(size_t)e * E + i];
    const int s = src_idx[(size_t)e * E + i];
    const int pos = atomicAdd(&g_cursor[c_ROFF[e] + d], 1);
    g_ebuf[pos] = c_OFF[c_ST[e]] + s;
}

// ---------------------------------------------------------------------------
// L1 fused aggregate+combine (validated)
// ---------------------------------------------------------------------------
__global__ void __launch_bounds__(256) l1_fused_kernel(
    __half* __restrict__ out1, const __half* __restrict__ wroot,
    int tOff, int Nn, int roff0, int roff1, int roff2, int R)
{
    __shared__ float smb[8][128];
    __shared__ float sma[8][256];

    const int warp = threadIdx.x >> 5;
    const int lane = threadIdx.x & 31;
    const int n = blockIdx.x * 8 + warp;
    if (n >= Nn) return;
    const int c4 = lane * 4;
    const int h  = lane >> 2;

    {
        const uint2 raw = *(const uint2*)(g_bases + (size_t)(tOff + n) * 128 + c4);
        const float2 lo = __half22float2(*(const __half2*)&raw.x);
        const float2 hi = __half22float2(*(const __half2*)&raw.y);
        smb[warp][c4 + 0] = lo.x; smb[warp][c4 + 1] = lo.y;
        smb[warp][c4 + 2] = hi.x; smb[warp][c4 + 3] = hi.y;
    }
    __syncwarp();

    float val[8];
    {
        const uint2 raw = *(const uint2*)(wroot + (size_t)n * 32 + h * 4);
        const float2 w01 = __half22float2(*(const __half2*)&raw.x);
        const float2 w23 = __half22float2(*(const __half2*)&raw.y);
#pragma unroll
        for (int j = 0; j < 8; j++) {
            const int dd = (lane * 8 + j) & 31;
            val[j] = w01.x * smb[warp][dd] + w01.y * smb[warp][32 + dd] +
                     w23.x * smb[warp][64 + dd] + w23.y * smb[warp][96 + dd];
        }
    }

    const int roffs[3] = {roff0, roff1, roff2};
    for (int r = 0; r < R; r++) {
        const int g = roffs[r] + n;
        const int rs = g_rowptr[g];
        const int re = g_rowptr[g + 1];
        const int ct = re - rs;
        float4 s4 = make_float4(0.f, 0.f, 0.f, 0.f);
        float4 m4 = make_float4(-INFINITY, -INFINITY, -INFINITY, -INFINITY);
        int idx = (rs < re) ? g_ebuf[rs] : 0;
        for (int k = rs; k < re; k++) {
            const int nidx = (k + 1 < re) ? g_ebuf[k + 1] : 0;
            const uint2 raw = *(const uint2*)(g_bases + (size_t)idx * 128 + c4);
            const float2 lo = __half22float2(*(const __half2*)&raw.x);
            const float2 hi = __half22float2(*(const __half2*)&raw.y);
            s4.x += lo.x; s4.y += lo.y; s4.z += hi.x; s4.w += hi.y;
            m4.x = fmaxf(m4.x, lo.x); m4.y = fmaxf(m4.y, lo.y);
            m4.z = fmaxf(m4.z, hi.x); m4.w = fmaxf(m4.w, hi.y);
            idx = nidx;
        }
        const float inv = 1.f / (float)(ct > 1 ? ct : 1);
        s4.x *= inv; s4.y *= inv; s4.z *= inv; s4.w *= inv;
        if (ct == 0) m4 = make_float4(0.f, 0.f, 0.f, 0.f);
        *(float4*)&sma[warp][c4]       = s4;
        *(float4*)&sma[warp][128 + c4] = m4;
        __syncwarp();
        const uint4 raw = *(const uint4*)(g_wrel + (size_t)g * 64 + h * 8);
        const float2 w01 = __half22float2(*(const __half2*)&raw.x);
        const float2 w23 = __half22float2(*(const __half2*)&raw.y);
        const float2 w45 = __half22float2(*(const __half2*)&raw.z);
        const float2 w67 = __half22float2(*(const __half2*)&raw.w);
        const float wv[8] = {w01.x, w01.y, w23.x, w23.y, w45.x, w45.y, w67.x, w67.y};
#pragma unroll
        for (int j = 0; j < 8; j++) {
            const int dd = (lane * 8 + j) & 31;
#pragma unroll
            for (int b = 0; b < 8; b++)
                val[j] += wv[b] * sma[warp][b * 32 + dd];
        }
        __syncwarp();
    }

    union { __half2 h[4]; uint4 u; } pk;
#pragma unroll
    for (int q = 0; q < 4; q++)
        pk.h[q] = __floats2half2_rn(fmaxf(val[2 * q], 0.f), fmaxf(val[2 * q + 1], 0.f));
    *(uint4*)(out1 + (size_t)n * 256 + lane * 8) = pk.u;
}

// ---------------------------------------------------------------------------
// L2 aggregation (validated)
// ---------------------------------------------------------------------------
__global__ void __launch_bounds__(256) l2_agg_kernel()
{
    const int warp = threadIdx.x >> 5;
    const int lane = threadIdx.x & 31;
    const int g = blockIdx.x * 8 + warp;
    if (g >= RTOT) return;
    const int c8 = lane * 8;
    const int rs = g_rowptr[g];
    const int re = g_rowptr[g + 1];
    const int ct = re - rs;
    float a[8];
#pragma unroll
    for (int j = 0; j < 8; j++) a[j] = 0.f;
    int idx = (rs < re) ? g_ebuf[rs] : 0;
    for (int k = rs; k < re; k++) {
        const int nidx = (k + 1 < re) ? g_ebuf[k + 1] : 0;
        const uint4 raw = *(const uint4*)(g_out1 + (size_t)idx * 256 + c8);
        const float2 v0 = __half22float2(*(const __half2*)&raw.x);
        const float2 v1 = __half22float2(*(const __half2*)&raw.y);
        const float2 v2 = __half22float2(*(const __half2*)&raw.z);
        const float2 v3 = __half22float2(*(const __half2*)&raw.w);
        a[0] += v0.x; a[1] += v0.y; a[2] += v1.x; a[3] += v1.y;
        a[4] += v2.x; a[5] += v2.y; a[6] += v3.x; a[7] += v3.y;
        idx = nidx;
    }
    const float inv = 1.f / (float)(ct > 1 ? ct : 1);
    union { __half2 h[4]; uint4 u; } pk;
#pragma unroll
    for (int q = 0; q < 4; q++)
        pk.h[q] = __floats2half2_rn(a[2 * q] * inv, a[2 * q + 1] * inv);
    *(uint4*)(g_sum2 + (size_t)g * 256 + c8) = pk.u;
}

// ---------------------------------------------------------------------------
// host
// ---------------------------------------------------------------------------
extern "C" void kernel_launch(void* const* d_in, const int* in_sizes, int n_in,
                              void* d_out, int out_size)
{
    const float* x_paper    = (const float*)d_in[0];
    const float* emb_author = (const float*)d_in[1];
    const float* emb_fos    = (const float*)d_in[2];
    const float* emb_inst   = (const float*)d_in[3];
    const float* bases_w1   = (const float*)d_in[4];
    const float* rel_w1     = (const float*)d_in[5];
    const float* rel_b1     = (const float*)d_in[6];
    const float* root_w1    = (const float*)d_in[7];
    const float* root_b1    = (const float*)d_in[8];
    const float* rel_w2     = (const float*)d_in[9];
    const float* root_w2    = (const float*)d_in[10];
    const float* root_b2    = (const float*)d_in[11];
    const int*   src_idx    = (const int*)d_in[12];
    const int*   dst_idx    = (const int*)d_in[13];
    float* out = (float*)d_out;

    static const int NUMSh[4] = {200000, 30000, 5000, 150000};
    static const int OFFh[4]  = {0, 200000, 230000, 235000};
    static const int DT[7] = {2, 0, 3, 0, 3, 1, 3};
    static const int ROFFh[7] = {0, 5000, 205000, 355000, 555000, 705000, 735000};

    __half *xh_p, *bases_p, *out1_p, *wroot_p, *wrel_p, *sum2_p, *w1p_p, *w2p_p;
    float* b1p_p;
    int* cnt_p;
    cudaGetSymbolAddress((void**)&xh_p,    g_xh);
    cudaGetSymbolAddress((void**)&bases_p, g_bases);
    cudaGetSymbolAddress((void**)&out1_p,  g_out1);
    cudaGetSymbolAddress((void**)&wroot_p, g_wroot);
    cudaGetSymbolAddress((void**)&wrel_p,  g_wrel);
    cudaGetSymbolAddress((void**)&sum2_p,  g_sum2);
    cudaGetSymbolAddress((void**)&w1p_p,   g_w1p);
    cudaGetSymbolAddress((void**)&b1p_p,   g_b1p);
    cudaGetSymbolAddress((void**)&w2p_p,   g_w2p);
    cudaGetSymbolAddress((void**)&cnt_p,   g_cnt);

    const float* xs[4] = {emb_author, emb_fos, emb_inst, x_paper};

    // ---- CSR build ----
    cudaMemsetAsync(cnt_p, 0, (size_t)RTOT * sizeof(int));
    {
        dim3 grid((E + 255) / 256, 7);
        count_kernel<<<grid, 256>>>(dst_idx);
    }
    scan1_kernel<<<(RTOT + 2047) / 2048, 256>>>();
    scan2_kernel<<<1, 512>>>((RTOT + 2047) / 2048);
    scan3_kernel<<<(RTOT + 1 + 255) / 256, 256>>>();
    {
        dim3 grid((E + 255) / 256, 7);
        fill_kernel<<<grid, 256>>>(src_idx, dst_idx);
    }

    // ---- prep ----
    for (int t = 0; t < 4; t++) {
        const int n = NUMSh[t] * 128;
        cvt_half<<<(n + 255) / 256, 256>>>(xs[t], xh_p + (size_t)OFFh[t] * 128, n);
    }
    int relsOf[4][3], Rof[4];
    for (int t = 0; t < 4; t++) {
        Rof[t] = 0;
        for (int e = 0; e < 7; e++)
            if (DT[e] == t) relsOf[t][Rof[t]++] = e;
        for (int r = Rof[t]; r < 3; r++) relsOf[t][r] = relsOf[t][0];
    }
    for (int t = 0; t < 4; t++) {
        pack_w1<<<(128 * NPAD + 255) / 256, 256>>>(
            bases_w1, root_w1, rel_w1, root_b1, rel_b1,
            w1p_p + (size_t)t * 128 * NPAD, b1p_p + (size_t)t * NPAD,
            t, Rof[t], relsOf[t][0], relsOf[t][1], relsOf[t][2]);
        const int nseg = 1 + Rof[t];
        pack_w2<<<(nseg * 256 * NPAD + 255) / 256, 256>>>(
            root_w2, rel_w2, w2p_p + (size_t)t * 1024 * NPAD,
            t, nseg, relsOf[t][0], relsOf[t][1], relsOf[t][2]);
    }

    // ---- layer-1 merged GEMM per type ----
    for (int t = 0; t < 4; t++) {
        const int Ncols = 160 + 64 * Rof[t];
        const __half* A = xh_p + (size_t)OFFh[t] * 128;
        dim3 grid((Ncols + 127) / 128, (NUMSh[t] + 127) / 128);
        hgemm_h<<<grid, 256>>>(
            A, A, A, A, w1p_p + (size_t)t * 128 * NPAD, b1p_p + (size_t)t * NPAD,
            out, NUMSh[t], 128, 16, 4, 1,
            OFFh[t], ROFFh[relsOf[t][0]], ROFFh[relsOf[t][1]], ROFFh[relsOf[t][2]],
            Ncols);
    }

    // ---- layer-1 fused aggregate+combine ----
    for (int t = 0; t < 4; t++) {
        l1_fused_kernel<<<(NUMSh[t] + 7) / 8, 256>>>(
            out1_p + (size_t)OFFh[t] * 256, wroot_p + (size_t)OFFh[t] * 32,
            OFFh[t], NUMSh[t],
            ROFFh[relsOf[t][0]], ROFFh[relsOf[t][1]], ROFFh[relsOf[t][2]], Rof[t]);
    }

    // ---- layer-2 aggregation ----
    l2_agg_kernel<<<(RTOT + 7) / 8, 256>>>();

    // ---- layer-2 multi-segment GEMM per type ----
    for (int t = 0; t < 4; t++) {
        const __half* A[4];
        A[0] = out1_p + (size_t)OFFh[t] * 256;
        int nseg = 1;
        for (int r = 0; r < Rof[t]; r++)
            A[nseg++] = sum2_p + (size_t)ROFFh[relsOf[t][r]] * 256;
        for (int s2 = nseg; s2 < 4; s2++) A[s2] = A[0];
        dim3 grid(3, (NUMSh[t] + 127) / 128);
        hgemm_h<<<grid, 256>>>(
            A[0], A[1], A[2], A[3], w2p_p + (size_t)t * 1024 * NPAD,
            root_b2 + (size_t)t * 349,
            out + (size_t)OFFh[t] * 349, NUMSh[t], 256, 3, nseg * 8, 0,
            0, 0, 0, 0, 349);
    }
}

// round 13
// speedup vs baseline: 1.1266x; 1.1266x over previous
#include <cuda_runtime.h>
#include <cuda_fp16.h>
#include <math.h>
#include <stdint.h>

// ---------------------------------------------------------------------------
// REGC hetero-GNN. Types [author 200000, fos 30000, inst 5000, paper 150000].
// 7 relations x 400000 edges. L1: 128->256 (H=8,NB=4,DH=32) mean+max.
// L2: 256->349 mean. fp16 HMMA GEMMs (register-prefetch + double-buffered
// smem, ONE sync/iter, BM=128 BN=64); CSR aggregation; fp16 intermediates.
// ---------------------------------------------------------------------------

#define E     400000
#define RTOT  885000
#define TOTE  2800000
#define NPAD  384

__device__ __half g_xh   [(size_t)385000 * 128];
__device__ __half g_bases[(size_t)385000 * 128];
__device__ __half g_out1 [(size_t)385000 * 256];   // post-ReLU
__device__ __half g_wroot[(size_t)385000 * 32];
__device__ __half g_wrel [(size_t)RTOT * 64];
__device__ __half g_sum2 [(size_t)RTOT * 256];
__device__ __half g_w1p  [4][(size_t)128 * NPAD];
__device__ float  g_b1p  [4][NPAD];
__device__ __half g_w2p  [4][(size_t)1024 * NPAD];
__device__ int    g_cnt   [RTOT];
__device__ int    g_rowptr[RTOT + 1];
__device__ int    g_cursor[RTOT];
__device__ int    g_ebuf  [TOTE];
__device__ int    g_bsum  [512];

__device__ __constant__ int c_ST[7]   = {0, 2, 0, 3, 3, 3, 1};
__device__ __constant__ int c_OFF[4]  = {0, 200000, 230000, 235000};
__device__ __constant__ int c_ROFF[7] = {0, 5000, 205000, 355000, 555000, 705000, 735000};

// ---------------------------------------------------------------------------
// fp16 GEMM: BM=128 BN=64 BK=32, 256 threads, warp tile 32x32 (4x2 warps).
// Double-buffered smem, register prefetch, ONE __syncthreads per K-iter.
// A: up to 4 fp16 row-segments, aStride halves/row. B: packed [nit*32][NPAD].
// mode 0: C f32 = acc + bias (L2 logits, row stride 349, scalar stores --
//         349 odd => vector stores misalign on odd rows)
// mode 1: scatter cols [0,128)->g_bases, [128,160)->g_wroot, [160,..)->g_wrel
// ---------------------------------------------------------------------------
__global__ void __launch_bounds__(256) hgemm_h(
    const __half* A0, const __half* A1, const __half* A2, const __half* A3,
    const __half* __restrict__ Bp, const float* __restrict__ bias,
    float* __restrict__ Cf,
    int M, int aStride, int segShift, int nit, int mode,
    int nodeOff, int ro0, int ro1, int ro2, int Ncols)
{
    __shared__ __align__(16) __half As[2][128][40];
    __shared__ __align__(16) __half Bs[2][32][72];

    const __half* Aseg[4] = {A0, A1, A2, A3};
    const int tid  = threadIdx.x;
    const int lane = tid & 31;
    const int warp = tid >> 5;
    const int wm = (warp & 3) * 32;
    const int wn = (warp >> 2) * 32;
    const int m0 = blockIdx.y * 128;
    const int n0 = blockIdx.x * 64;

    // A: 128 rows x 32 halves; thread -> (row, 16-half chunk)
    const int am = tid >> 1;
    const int ak = (tid & 1) * 16;
    // B: 32 rows x 64 halves; thread -> (krow, 8-half chunk)
    const int bk = tid >> 3;
    const int bn = (tid & 7) * 8;

    uint4 pa0, pa1, pb;

    auto load_g = [&](int it) {
        const int seg = it >> segShift;
        const int k0 = (it - (seg << segShift)) * 32;
        const int gm = m0 + am;
        const __half* ap = Aseg[seg] + (size_t)(gm < M ? gm : 0) * aStride + k0 + ak;
        pa0 = *(const uint4*)ap;
        pa1 = *(const uint4*)(ap + 8);
        pb  = *(const uint4*)(Bp + (size_t)(it * 32 + bk) * NPAD + n0 + bn);
    };
    auto store_s = [&](int st) {
        *(uint4*)&As[st][am][ak]     = pa0;
        *(uint4*)&As[st][am][ak + 8] = pa1;
        *(uint4*)&Bs[st][bk][bn]     = pb;
    };

    float acc[2][4][4];
#pragma unroll
    for (int mi = 0; mi < 2; mi++)
#pragma unroll
        for (int nj = 0; nj < 4; nj++)
#pragma unroll
            for (int r = 0; r < 4; r++) acc[mi][nj][r] = 0.f;

    const uint32_t sA = (uint32_t)__cvta_generic_to_shared(&As[0][0][0]);
    const uint32_t sB = (uint32_t)__cvta_generic_to_shared(&Bs[0][0][0]);
    const uint32_t aOff = (uint32_t)((wm + (lane & 15)) * 80 + ((lane >> 4) * 8) * 2);
    const uint32_t bOff = (uint32_t)(((lane & 15)) * 144 + (wn + (lane >> 4) * 8) * 2);

    auto compute = [&](int st) {
        const uint32_t aAddr0 = sA + (uint32_t)(st * 128 * 40 * 2) + aOff;
        const uint32_t bAddr0 = sB + (uint32_t)(st * 32 * 72 * 2) + bOff;
#pragma unroll
        for (int kk = 0; kk < 2; kk++) {
            uint32_t a[2][4], b[4][2];
#pragma unroll
            for (int mi = 0; mi < 2; mi++) {
                uint32_t addr = aAddr0 + (uint32_t)(mi * 16 * 80 + kk * 16 * 2);
                asm volatile("ldmatrix.sync.aligned.m8n8.x4.shared.b16 {%0,%1,%2,%3}, [%4];"
                             : "=r"(a[mi][0]), "=r"(a[mi][1]), "=r"(a[mi][2]), "=r"(a[mi][3])
                             : "r"(addr));
            }
#pragma unroll
            for (int njp = 0; njp < 2; njp++) {
                uint32_t addr = bAddr0 + (uint32_t)(kk * 16 * 144 + njp * 16 * 2);
                asm volatile("ldmatrix.sync.aligned.m8n8.x4.trans.shared.b16 {%0,%1,%2,%3}, [%4];"
                             : "=r"(b[njp * 2][0]), "=r"(b[njp * 2][1]),
                               "=r"(b[njp * 2 + 1][0]), "=r"(b[njp * 2 + 1][1])
                             : "r"(addr));
            }
#pragma unroll
            for (int mi = 0; mi < 2; mi++)
#pragma unroll
                for (int nj = 0; nj < 4; nj++) {
                    asm volatile(
                        "mma.sync.aligned.m16n8k16.row.col.f32.f16.f16.f32 "
                        "{%0,%1,%2,%3}, {%4,%5,%6,%7}, {%8,%9}, {%0,%1,%2,%3};"
                        : "+f"(acc[mi][nj][0]), "+f"(acc[mi][nj][1]),
                          "+f"(acc[mi][nj][2]), "+f"(acc[mi][nj][3])
                        : "r"(a[mi][0]), "r"(a[mi][1]), "r"(a[mi][2]), "r"(a[mi][3]),
                          "r"(b[nj][0]), "r"(b[nj][1]));
                }
        }
    };

    // double-buffered mainloop: ONE sync per iteration
    load_g(0);
    store_s(0);
    __syncthreads();
    int cur = 0;
    for (int it = 1; it < nit; it++) {
        load_g(it);
        store_s(cur ^ 1);   // buffer last read before previous iter's barrier
        compute(cur);
        __syncthreads();
        cur ^= 1;
    }
    compute(cur);

    // ---- epilogue ----
#pragma unroll
    for (int mi = 0; mi < 2; mi++)
#pragma unroll
        for (int nj = 0; nj < 4; nj++)
#pragma unroll
            for (int rp = 0; rp < 2; rp++) {
                const int row = m0 + wm + mi * 16 + (lane >> 2) + rp * 8;
                const int col = n0 + wn + nj * 8 + (lane & 3) * 2;
                if (row >= M || col >= Ncols) continue;
                const bool pair = (col + 1 < Ncols);
                const float v0 = acc[mi][nj][rp * 2 + 0] + bias[col];
                const float v1 = acc[mi][nj][rp * 2 + 1] + bias[pair ? col + 1 : col];
                if (mode == 0) {
                    float* p = Cf + (size_t)row * 349 + col;
                    p[0] = v0;
                    if (pair) p[1] = v1;
                } else {
                    const __half2 h2 = __floats2half2_rn(v0, v1);
                    if (col < 128) {
                        *(__half2*)(g_bases + (size_t)(nodeOff + row) * 128 + col) = h2;
                    } else if (col < 160) {
                        *(__half2*)(g_wroot + (size_t)(nodeOff + row) * 32 + (col - 128)) = h2;
                    } else {
                        const int cc = col - 160;
                        const int rr = cc >> 6;
                        const int ro = (rr == 0) ? ro0 : ((rr == 1) ? ro1 : ro2);
                        *(__half2*)(g_wrel + (size_t)(ro + row) * 64 + (cc & 63)) = h2;
                    }
                }
            }
}

// ---------------------------------------------------------------------------
// prep kernels (validated R8/R11)
// ---------------------------------------------------------------------------
__global__ void cvt_half(const float* __restrict__ x, __half* __restrict__ y, int n)
{
    const int i = blockIdx.x * blockDim.x + threadIdx.x;
    if (i < n) y[i] = __float2half_rn(x[i]);
}

__global__ void pack_w1(const float* __restrict__ bases_w1,
                        const float* __restrict__ root_w1,
                        const float* __restrict__ rel_w1,
                        const float* __restrict__ root_b1,
                        const float* __restrict__ rel_b1,
                        __half* __restrict__ w1p, float* __restrict__ b1p,
                        int t, int R, int e0, int e1, int e2)
{
    const int i = blockIdx.x * blockDim.x + threadIdx.x;
    if (i >= 128 * NPAD) return;
    const int k = i / NPAD, n = i % NPAD;
    float v = 0.f, b = 0.f;
    if (n < 128) {
        v = bases_w1[k * 128 + n];
    } else if (n < 160) {
        v = root_w1[((size_t)t * 32 + (n - 128)) * 128 + k];
        b = root_b1[t * 32 + (n - 128)];
    } else {
        const int cc = n - 160;
        const int r = cc >> 6;
        if (r < R) {
            const int e = (r == 0) ? e0 : ((r == 1) ? e1 : e2);
            v = rel_w1[((size_t)e * 64 + (cc & 63)) * 128 + k];
            b = rel_b1[e * 64 + (cc & 63)];
        }
    }
    w1p[(size_t)k * NPAD + n] = __float2half_rn(v);
    if (k == 0) b1p[n] = b;
}

__global__ void pack_w2(const float* __restrict__ root_w2,
                        const float* __restrict__ rel_w2,
                        __half* __restrict__ w2p,
                        int t, int nseg, int e1, int e2, int e3)
{
    const int i = blockIdx.x * blockDim.x + threadIdx.x;
    if (i >= nseg * 256 * NPAD) return;
    const int kg = i / NPAD, n = i % NPAD;
    const int seg = kg >> 8, k = kg & 255;
    float v = 0.f;
    if (n < 349) {
        if (seg == 0) v = root_w2[((size_t)t * 349 + n) * 256 + k];
        else {
            const int e = (seg == 1) ? e1 : ((seg == 2) ? e2 : e3);
            v = rel_w2[((size_t)e * 349 + n) * 256 + k];
        }
    }
    w2p[(size_t)kg * NPAD + n] = __float2half_rn(v);
}

// ---------------------------------------------------------------------------
// CSR build (validated R5-R11)
// ---------------------------------------------------------------------------
__global__ void count_kernel(const int* __restrict__ dst_idx)
{
    const int e = blockIdx.y;
    const int i = blockIdx.x * blockDim.x + threadIdx.x;
    if (i >= E) return;
    atomicAdd(&g_cnt[c_ROFF[e] + dst_idx[(size_t)e * E + i]], 1);
}

__global__ void __launch_bounds__(256) scan1_kernel()
{
    __shared__ int s[256];
    const int tid = threadIdx.x;
    const int tbase = blockIdx.x * 2048 + tid * 8;
    int vals[8];
    int tsum = 0;
#pragma unroll
    for (int j = 0; j < 8; j++) {
        int v = (tbase + j < RTOT) ? g_cnt[tbase + j] : 0;
        vals[j] = tsum;
        tsum += v;
    }
    s[tid] = tsum;
    __syncthreads();
    for (int off = 1; off < 256; off <<= 1) {
        int t = (tid >= off) ? s[tid - off] : 0;
        __syncthreads();
        s[tid] += t;
        __syncthreads();
    }
    const int texcl = (tid > 0) ? s[tid - 1] : 0;
    if (tid == 255) g_bsum[blockIdx.x] = s[255];
#pragma unroll
    for (int j = 0; j < 8; j++)
        if (tbase + j < RTOT) g_rowptr[tbase + j] = vals[j] + texcl;
}

__global__ void __launch_bounds__(512) scan2_kernel(int nb)
{
    __shared__ int s[512];
    const int tid = threadIdx.x;
    s[tid] = (tid < nb) ? g_bsum[tid] : 0;
    __syncthreads();
    for (int off = 1; off < 512; off <<= 1) {
        int t = (tid >= off) ? s[tid - off] : 0;
        __syncthreads();
        s[tid] += t;
        __syncthreads();
    }
    g_bsum[tid] = (tid > 0) ? s[tid - 1] : 0;
}

__global__ void scan3_kernel()
{
    const int i = blockIdx.x * blockDim.x + threadIdx.x;
    if (i < RTOT) {
        int v = g_rowptr[i] + g_bsum[i >> 11];
        g_rowptr[i] = v;
        g_cursor[i] = v;
    } else if (i == RTOT) {
        g_rowptr[RTOT] = TOTE;
    }
}

__global__ void fill_kernel(const int* __restrict__ src_idx,
                            const int* __restrict__ dst_idx)
{
    const int e = blockIdx.y;
    const int i = blockIdx.x * blockDim.x + threadIdx.x;
    if (i >= E) return;
    const int d = dst_idx[(size_t)e * E + i];
    const int s = src_idx[(size_t)e * E + i];
    const int pos = atomicAdd(&g_cursor[c_ROFF[e] + d], 1);
    g_ebuf[pos] = c_OFF[c_ST[e]] + s;
}

// ---------------------------------------------------------------------------
// L1 fused aggregate+combine (validated)
// ---------------------------------------------------------------------------
__global__ void __launch_bounds__(256) l1_fused_kernel(
    __half* __restrict__ out1, const __half* __restrict__ wroot,
    int tOff, int Nn, int roff0, int roff1, int roff2, int R)
{
    __shared__ float smb[8][128];
    __shared__ float sma[8][256];

    const int warp = threadIdx.x >> 5;
    const int lane = threadIdx.x & 31;
    const int n = blockIdx.x * 8 + warp;
    if (n >= Nn) return;
    const int c4 = lane * 4;
    const int h  = lane >> 2;

    {
        const uint2 raw = *(const uint2*)(g_bases + (size_t)(tOff + n) * 128 + c4);
        const float2 lo = __half22float2(*(const __half2*)&raw.x);
        const float2 hi = __half22float2(*(const __half2*)&raw.y);
        smb[warp][c4 + 0] = lo.x; smb[warp][c4 + 1] = lo.y;
        smb[warp][c4 + 2] = hi.x; smb[warp][c4 + 3] = hi.y;
    }
    __syncwarp();

    float val[8];
    {
        const uint2 raw = *(const uint2*)(wroot + (size_t)n * 32 + h * 4);
        const float2 w01 = __half22float2(*(const __half2*)&raw.x);
        const float2 w23 = __half22float2(*(const __half2*)&raw.y);
#pragma unroll
        for (int j = 0; j < 8; j++) {
            const int dd = (lane * 8 + j) & 31;
            val[j] = w01.x * smb[warp][dd] + w01.y * smb[warp][32 + dd] +
                     w23.x * smb[warp][64 + dd] + w23.y * smb[warp][96 + dd];
        }
    }

    const int roffs[3] = {roff0, roff1, roff2};
    for (int r = 0; r < R; r++) {
        const int g = roffs[r] + n;
        const int rs = g_rowptr[g];
        const int re = g_rowptr[g + 1];
        const int ct = re - rs;
        float4 s4 = make_float4(0.f, 0.f, 0.f, 0.f);
        float4 m4 = make_float4(-INFINITY, -INFINITY, -INFINITY, -INFINITY);
        int idx = (rs < re) ? g_ebuf[rs] : 0;
        for (int k = rs; k < re; k++) {
            const int nidx = (k + 1 < re) ? g_ebuf[k + 1] : 0;
            const uint2 raw = *(const uint2*)(g_bases + (size_t)idx * 128 + c4);
            const float2 lo = __half22float2(*(const __half2*)&raw.x);
            const float2 hi = __half22float2(*(const __half2*)&raw.y);
            s4.x += lo.x; s4.y += lo.y; s4.z += hi.x; s4.w += hi.y;
            m4.x = fmaxf(m4.x, lo.x); m4.y = fmaxf(m4.y, lo.y);
            m4.z = fmaxf(m4.z, hi.x); m4.w = fmaxf(m4.w, hi.y);
            idx = nidx;
        }
        const float inv = 1.f / (float)(ct > 1 ? ct : 1);
        s4.x *= inv; s4.y *= inv; s4.z *= inv; s4.w *= inv;
        if (ct == 0) m4 = make_float4(0.f, 0.f, 0.f, 0.f);
        *(float4*)&sma[warp][c4]       = s4;
        *(float4*)&sma[warp][128 + c4] = m4;
        __syncwarp();
        const uint4 raw = *(const uint4*)(g_wrel + (size_t)g * 64 + h * 8);
        const float2 w01 = __half22float2(*(const __half2*)&raw.x);
        const float2 w23 = __half22float2(*(const __half2*)&raw.y);
        const float2 w45 = __half22float2(*(const __half2*)&raw.z);
        const float2 w67 = __half22float2(*(const __half2*)&raw.w);
        const float wv[8] = {w01.x, w01.y, w23.x, w23.y, w45.x, w45.y, w67.x, w67.y};
#pragma unroll
        for (int j = 0; j < 8; j++) {
            const int dd = (lane * 8 + j) & 31;
#pragma unroll
            for (int b = 0; b < 8; b++)
                val[j] += wv[b] * sma[warp][b * 32 + dd];
        }
        __syncwarp();
    }

    union { __half2 h[4]; uint4 u; } pk;
#pragma unroll
    for (int q = 0; q < 4; q++)
        pk.h[q] = __floats2half2_rn(fmaxf(val[2 * q], 0.f), fmaxf(val[2 * q + 1], 0.f));
    *(uint4*)(out1 + (size_t)n * 256 + lane * 8) = pk.u;
}

// ---------------------------------------------------------------------------
// L2 aggregation (validated)
// ---------------------------------------------------------------------------
__global__ void __launch_bounds__(256) l2_agg_kernel()
{
    const int warp = threadIdx.x >> 5;
    const int lane = threadIdx.x & 31;
    const int g = blockIdx.x * 8 + warp;
    if (g >= RTOT) return;
    const int c8 = lane * 8;
    const int rs = g_rowptr[g];
    const int re = g_rowptr[g + 1];
    const int ct = re - rs;
    float a[8];
#pragma unroll
    for (int j = 0; j < 8; j++) a[j] = 0.f;
    int idx = (rs < re) ? g_ebuf[rs] : 0;
    for (int k = rs; k < re; k++) {
        const int nidx = (k + 1 < re) ? g_ebuf[k + 1] : 0;
        const uint4 raw = *(const uint4*)(g_out1 + (size_t)idx * 256 + c8);
        const float2 v0 = __half22float2(*(const __half2*)&raw.x);
        const float2 v1 = __half22float2(*(const __half2*)&raw.y);
        const float2 v2 = __half22float2(*(const __half2*)&raw.z);
        const float2 v3 = __half22float2(*(const __half2*)&raw.w);
        a[0] += v0.x; a[1] += v0.y; a[2] += v1.x; a[3] += v1.y;
        a[4] += v2.x; a[5] += v2.y; a[6] += v3.x; a[7] += v3.y;
        idx = nidx;
    }
    const float inv = 1.f / (float)(ct > 1 ? ct : 1);
    union { __half2 h[4]; uint4 u; } pk;
#pragma unroll
    for (int q = 0; q < 4; q++)
        pk.h[q] = __floats2half2_rn(a[2 * q] * inv, a[2 * q + 1] * inv);
    *(uint4*)(g_sum2 + (size_t)g * 256 + c8) = pk.u;
}

// ---------------------------------------------------------------------------
// host
// ---------------------------------------------------------------------------
extern "C" void kernel_launch(void* const* d_in, const int* in_sizes, int n_in,
                              void* d_out, int out_size)
{
    const float* x_paper    = (const float*)d_in[0];
    const float* emb_author = (const float*)d_in[1];
    const float* emb_fos    = (const float*)d_in[2];
    const float* emb_inst   = (const float*)d_in[3];
    const float* bases_w1   = (const float*)d_in[4];
    const float* rel_w1     = (const float*)d_in[5];
    const float* rel_b1     = (const float*)d_in[6];
    const float* root_w1    = (const float*)d_in[7];
    const float* root_b1    = (const float*)d_in[8];
    const float* rel_w2     = (const float*)d_in[9];
    const float* root_w2    = (const float*)d_in[10];
    const float* root_b2    = (const float*)d_in[11];
    const int*   src_idx    = (const int*)d_in[12];
    const int*   dst_idx    = (const int*)d_in[13];
    float* out = (float*)d_out;

    static const int NUMSh[4] = {200000, 30000, 5000, 150000};
    static const int OFFh[4]  = {0, 200000, 230000, 235000};
    static const int DT[7] = {2, 0, 3, 0, 3, 1, 3};
    static const int ROFFh[7] = {0, 5000, 205000, 355000, 555000, 705000, 735000};

    __half *xh_p, *bases_p, *out1_p, *wroot_p, *wrel_p, *sum2_p, *w1p_p, *w2p_p;
    float* b1p_p;
    int* cnt_p;
    cudaGetSymbolAddress((void**)&xh_p,    g_xh);
    cudaGetSymbolAddress((void**)&bases_p, g_bases);
    cudaGetSymbolAddress((void**)&out1_p,  g_out1);
    cudaGetSymbolAddress((void**)&wroot_p, g_wroot);
    cudaGetSymbolAddress((void**)&wrel_p,  g_wrel);
    cudaGetSymbolAddress((void**)&sum2_p,  g_sum2);
    cudaGetSymbolAddress((void**)&w1p_p,   g_w1p);
    cudaGetSymbolAddress((void**)&b1p_p,   g_b1p);
    cudaGetSymbolAddress((void**)&w2p_p,   g_w2p);
    cudaGetSymbolAddress((void**)&cnt_p,   g_cnt);

    const float* xs[4] = {emb_author, emb_fos, emb_inst, x_paper};

    // ---- CSR build ----
    cudaMemsetAsync(cnt_p, 0, (size_t)RTOT * sizeof(int));
    {
        dim3 grid((E + 255) / 256, 7);
        count_kernel<<<grid, 256>>>(dst_idx);
    }
    scan1_kernel<<<(RTOT + 2047) / 2048, 256>>>();
    scan2_kernel<<<1, 512>>>((RTOT + 2047) / 2048);
    scan3_kernel<<<(RTOT + 1 + 255) / 256, 256>>>();
    {
        dim3 grid((E + 255) / 256, 7);
        fill_kernel<<<grid, 256>>>(src_idx, dst_idx);
    }

    // ---- prep ----
    for (int t = 0; t < 4; t++) {
        const int n = NUMSh[t] * 128;
        cvt_half<<<(n + 255) / 256, 256>>>(xs[t], xh_p + (size_t)OFFh[t] * 128, n);
    }
    int relsOf[4][3], Rof[4];
    for (int t = 0; t < 4; t++) {
        Rof[t] = 0;
        for (int e = 0; e < 7; e++)
            if (DT[e] == t) relsOf[t][Rof[t]++] = e;
        for (int r = Rof[t]; r < 3; r++) relsOf[t][r] = relsOf[t][0];
    }
    for (int t = 0; t < 4; t++) {
        pack_w1<<<(128 * NPAD + 255) / 256, 256>>>(
            bases_w1, root_w1, rel_w1, root_b1, rel_b1,
            w1p_p + (size_t)t * 128 * NPAD, b1p_p + (size_t)t * NPAD,
            t, Rof[t], relsOf[t][0], relsOf[t][1], relsOf[t][2]);
        const int nseg = 1 + Rof[t];
        pack_w2<<<(nseg * 256 * NPAD + 255) / 256, 256>>>(
            root_w2, rel_w2, w2p_p + (size_t)t * 1024 * NPAD,
            t, nseg, relsOf[t][0], relsOf[t][1], relsOf[t][2]);
    }

    // ---- layer-1 merged GEMM per type ----
    for (int t = 0; t < 4; t++) {
        const int Ncols = 160 + 64 * Rof[t];
        const __half* A = xh_p + (size_t)OFFh[t] * 128;
        dim3 grid((Ncols + 63) / 64, (NUMSh[t] + 127) / 128);
        hgemm_h<<<grid, 256>>>(
            A, A, A, A, w1p_p + (size_t)t * 128 * NPAD, b1p_p + (size_t)t * NPAD,
            out, NUMSh[t], 128, 16, 4, 1,
            OFFh[t], ROFFh[relsOf[t][0]], ROFFh[relsOf[t][1]], ROFFh[relsOf[t][2]],
            Ncols);
    }

    // ---- layer-1 fused aggregate+combine ----
    for (int t = 0; t < 4; t++) {
        l1_fused_kernel<<<(NUMSh[t] + 7) / 8, 256>>>(
            out1_p + (size_t)OFFh[t] * 256, wroot_p + (size_t)OFFh[t] * 32,
            OFFh[t], NUMSh[t],
            ROFFh[relsOf[t][0]], ROFFh[relsOf[t][1]], ROFFh[relsOf[t][2]], Rof[t]);
    }

    // ---- layer-2 aggregation ----
    l2_agg_kernel<<<(RTOT + 7) / 8, 256>>>();

    // ---- layer-2 multi-segment GEMM per type ----
    for (int t = 0; t < 4; t++) {
        const __half* A[4];
        A[0] = out1_p + (size_t)OFFh[t] * 256;
        int nseg = 1;
        for (int r = 0; r < Rof[t]; r++)
            A[nseg++] = sum2_p + (size_t)ROFFh[relsOf[t][r]] * 256;
        for (int s2 = nseg; s2 < 4; s2++) A[s2] = A[0];
        dim3 grid(6, (NUMSh[t] + 127) / 128);
        hgemm_h<<<grid, 256>>>(
            A[0], A[1], A[2], A[3], w2p_p + (size_t)t * 1024 * NPAD,
            root_b2 + (size_t)t * 349,
            out + (size_t)OFFh[t] * 349, NUMSh[t], 256, 3, nseg * 8, 0,
            0, 0, 0, 0, 349);
    }
}

// round 15
// speedup vs baseline: 1.7388x; 1.5433x over previous
#include <cuda_runtime.h>
#include <cuda_fp16.h>
#include <math.h>
#include <stdint.h>

// ---------------------------------------------------------------------------
// REGC hetero-GNN. Types [author 200000, fos 30000, inst 5000, paper 150000].
// 7 relations x 400000 edges. L1: 128->256 (H=8,NB=4,DH=32) mean+max.
// L2: 256->349 mean. fp16 HMMA GEMMs (R11-frozen register-prefetch mainloop,
// packed fp16 weights, BM=128 BN=64); CSR aggregation with 2-way unrolled
// gather loops (2x MLP); fp16 intermediates.
// ---------------------------------------------------------------------------

#define E     400000
#define RTOT  885000
#define TOTE  2800000
#define NPAD  384

__device__ __half g_xh   [(size_t)385000 * 128];
__device__ __half g_bases[(size_t)385000 * 128];
__device__ __half g_out1 [(size_t)385000 * 256];   // post-ReLU
__device__ __half g_wroot[(size_t)385000 * 32];
__device__ __half g_wrel [(size_t)RTOT * 64];
__device__ __half g_sum2 [(size_t)RTOT * 256];
__device__ __half g_w1p  [4][(size_t)128 * NPAD];
__device__ float  g_b1p  [4][NPAD];
__device__ __half g_w2p  [4][(size_t)1024 * NPAD];
__device__ int    g_cnt   [RTOT];
__device__ int    g_rowptr[RTOT + 1];
__device__ int    g_cursor[RTOT];
__device__ int    g_ebuf  [TOTE];
__device__ int    g_bsum  [512];

__device__ __constant__ int c_ST[7]   = {0, 2, 0, 3, 3, 3, 1};
__device__ __constant__ int c_OFF[4]  = {0, 200000, 230000, 235000};
__device__ __constant__ int c_ROFF[7] = {0, 5000, 205000, 355000, 555000, 705000, 735000};

// ---------------------------------------------------------------------------
// fp16 GEMM (R11-frozen): BM=128 BN=64 BK=32, 256 threads, warp tile 32x32.
// Register prefetch, two syncs/iter. DO NOT MODIFY — R12 (BN=128) and R13
// (double-buffer) both regressed vs this structure.
// A: up to 4 fp16 row-segments, aStride halves/row. B: packed [nit*32][NPAD].
// mode 0: C f32 = acc + bias (L2 logits, row stride 349, scalar stores)
// mode 1: scatter cols [0,128)->g_bases, [128,160)->g_wroot, [160,..)->g_wrel
// ---------------------------------------------------------------------------
__global__ void __launch_bounds__(256) hgemm_h(
    const __half* A0, const __half* A1, const __half* A2, const __half* A3,
    const __half* __restrict__ Bp, const float* __restrict__ bias,
    float* __restrict__ Cf,
    int M, int aStride, int segShift, int nit, int mode,
    int nodeOff, int ro0, int ro1, int ro2, int Ncols)
{
    __shared__ __align__(16) __half As[128][40];
    __shared__ __align__(16) __half Bs[32][72];

    const __half* Aseg[4] = {A0, A1, A2, A3};
    const int tid  = threadIdx.x;
    const int lane = tid & 31;
    const int warp = tid >> 5;
    const int wm = (warp & 3) * 32;
    const int wn = (warp >> 2) * 32;
    const int m0 = blockIdx.y * 128;
    const int n0 = blockIdx.x * 64;

    const int am = tid >> 1;
    const int ak = (tid & 1) * 16;
    const int bk = tid >> 3;
    const int bn = (tid & 7) * 8;

    uint4 pa0, pa1, pb;

    auto load_g = [&](int it) {
        const int seg = it >> segShift;
        const int k0 = (it - (seg << segShift)) * 32;
        const int gm = m0 + am;
        const __half* ap = Aseg[seg] + (size_t)(gm < M ? gm : 0) * aStride + k0 + ak;
        pa0 = *(const uint4*)ap;
        pa1 = *(const uint4*)(ap + 8);
        pb  = *(const uint4*)(Bp + (size_t)(it * 32 + bk) * NPAD + n0 + bn);
    };
    auto store_s = [&]() {
        *(uint4*)&As[am][ak]     = pa0;
        *(uint4*)&As[am][ak + 8] = pa1;
        *(uint4*)&Bs[bk][bn]     = pb;
    };

    float acc[2][4][4];
#pragma unroll
    for (int mi = 0; mi < 2; mi++)
#pragma unroll
        for (int nj = 0; nj < 4; nj++)
#pragma unroll
            for (int r = 0; r < 4; r++) acc[mi][nj][r] = 0.f;

    const uint32_t sA = (uint32_t)__cvta_generic_to_shared(&As[0][0]);
    const uint32_t sB = (uint32_t)__cvta_generic_to_shared(&Bs[0][0]);
    const uint32_t aAddr0 = sA + (uint32_t)((wm + (lane & 15)) * 80 + ((lane >> 4) * 8) * 2);
    const uint32_t bAddr0 = sB + (uint32_t)(((lane & 15)) * 144 + (wn + (lane >> 4) * 8) * 2);

    auto compute = [&]() {
#pragma unroll
        for (int kk = 0; kk < 2; kk++) {
            uint32_t a[2][4], b[4][2];
#pragma unroll
            for (int mi = 0; mi < 2; mi++) {
                uint32_t addr = aAddr0 + (uint32_t)(mi * 16 * 80 + kk * 16 * 2);
                asm volatile("ldmatrix.sync.aligned.m8n8.x4.shared.b16 {%0,%1,%2,%3}, [%4];"
                             : "=r"(a[mi][0]), "=r"(a[mi][1]), "=r"(a[mi][2]), "=r"(a[mi][3])
                             : "r"(addr));
            }
#pragma unroll
            for (int njp = 0; njp < 2; njp++) {
                uint32_t addr = bAddr0 + (uint32_t)(kk * 16 * 144 + njp * 16 * 2);
                asm volatile("ldmatrix.sync.aligned.m8n8.x4.trans.shared.b16 {%0,%1,%2,%3}, [%4];"
                             : "=r"(b[njp * 2][0]), "=r"(b[njp * 2][1]),
                               "=r"(b[njp * 2 + 1][0]), "=r"(b[njp * 2 + 1][1])
                             : "r"(addr));
            }
#pragma unroll
            for (int mi = 0; mi < 2; mi++)
#pragma unroll
                for (int nj = 0; nj < 4; nj++) {
                    asm volatile(
                        "mma.sync.aligned.m16n8k16.row.col.f32.f16.f16.f32 "
                        "{%0,%1,%2,%3}, {%4,%5,%6,%7}, {%8,%9}, {%0,%1,%2,%3};"
                        : "+f"(acc[mi][nj][0]), "+f"(acc[mi][nj][1]),
                          "+f"(acc[mi][nj][2]), "+f"(acc[mi][nj][3])
                        : "r"(a[mi][0]), "r"(a[mi][1]), "r"(a[mi][2]), "r"(a[mi][3]),
                          "r"(b[nj][0]), "r"(b[nj][1]));
                }
        }
    };

    load_g(0);
    store_s();
    __syncthreads();
    for (int it = 1; it < nit; it++) {
        load_g(it);
        compute();
        __syncthreads();
        store_s();
        __syncthreads();
    }
    compute();

    // ---- epilogue ----
#pragma unroll
    for (int mi = 0; mi < 2; mi++)
#pragma unroll
        for (int nj = 0; nj < 4; nj++)
#pragma unroll
            for (int rp = 0; rp < 2; rp++) {
                const int row = m0 + wm + mi * 16 + (lane >> 2) + rp * 8;
                const int col = n0 + wn + nj * 8 + (lane & 3) * 2;
                if (row >= M || col >= Ncols) continue;
                const bool pair = (col + 1 < Ncols);
                const float v0 = acc[mi][nj][rp * 2 + 0] + bias[col];
                const float v1 = acc[mi][nj][rp * 2 + 1] + bias[pair ? col + 1 : col];
                if (mode == 0) {
                    float* p = Cf + (size_t)row * 349 + col;
                    p[0] = v0;
                    if (pair) p[1] = v1;
                } else {
                    const __half2 h2 = __floats2half2_rn(v0, v1);
                    if (col < 128) {
                        *(__half2*)(g_bases + (size_t)(nodeOff + row) * 128 + col) = h2;
                    } else if (col < 160) {
                        *(__half2*)(g_wroot + (size_t)(nodeOff + row) * 32 + (col - 128)) = h2;
                    } else {
                        const int cc = col - 160;
                        const int rr = cc >> 6;
                        const int ro = (rr == 0) ? ro0 : ((rr == 1) ? ro1 : ro2);
                        *(__half2*)(g_wrel + (size_t)(ro + row) * 64 + (cc & 63)) = h2;
                    }
                }
            }
}

// ---------------------------------------------------------------------------
// prep kernels (validated)
// ---------------------------------------------------------------------------
__global__ void cvt_half(const float* __restrict__ x, __half* __restrict__ y, int n)
{
    const int i = blockIdx.x * blockDim.x + threadIdx.x;
    if (i < n) y[i] = __float2half_rn(x[i]);
}

__global__ void pack_w1(const float* __restrict__ bases_w1,
                        const float* __restrict__ root_w1,
                        const float* __restrict__ rel_w1,
                        const float* __restrict__ root_b1,
                        const float* __restrict__ rel_b1,
                        __half* __restrict__ w1p, float* __restrict__ b1p,
                        int t, int R, int e0, int e1, int e2)
{
    const int i = blockIdx.x * blockDim.x + threadIdx.x;
    if (i >= 128 * NPAD) return;
    const int k = i / NPAD, n = i % NPAD;
    float v = 0.f, b = 0.f;
    if (n < 128) {
        v = bases_w1[k * 128 + n];
    } else if (n < 160) {
        v = root_w1[((size_t)t * 32 + (n - 128)) * 128 + k];
        b = root_b1[t * 32 + (n - 128)];
    } else {
        const int cc = n - 160;
        const int r = cc >> 6;
        if (r < R) {
            const int e = (r == 0) ? e0 : ((r == 1) ? e1 : e2);
            v = rel_w1[((size_t)e * 64 + (cc & 63)) * 128 + k];
            b = rel_b1[e * 64 + (cc & 63)];
        }
    }
    w1p[(size_t)k * NPAD + n] = __float2half_rn(v);
    if (k == 0) b1p[n] = b;
}

__global__ void pack_w2(const float* __restrict__ root_w2,
                        const float* __restrict__ rel_w2,
                        __half* __restrict__ w2p,
                        int t, int nseg, int e1, int e2, int e3)
{
    const int i = blockIdx.x * blockDim.x + threadIdx.x;
    if (i >= nseg * 256 * NPAD) return;
    const int kg = i / NPAD, n = i % NPAD;
    const int seg = kg >> 8, k = kg & 255;
    float v = 0.f;
    if (n < 349) {
        if (seg == 0) v = root_w2[((size_t)t * 349 + n) * 256 + k];
        else {
            const int e = (seg == 1) ? e1 : ((seg == 2) ? e2 : e3);
            v = rel_w2[((size_t)e * 349 + n) * 256 + k];
        }
    }
    w2p[(size_t)kg * NPAD + n] = __float2half_rn(v);
}

// ---------------------------------------------------------------------------
// CSR build (validated)
// ---------------------------------------------------------------------------
__global__ void count_kernel(const int* __restrict__ dst_idx)
{
    const int e = blockIdx.y;
    const int i = blockIdx.x * blockDim.x + threadIdx.x;
    if (i >= E) return;
    atomicAdd(&g_cnt[c_ROFF[e] + dst_idx[(size_t)e * E + i]], 1);
}

__global__ void __launch_bounds__(256) scan1_kernel()
{
    __shared__ int s[256];
    const int tid = threadIdx.x;
    const int tbase = blockIdx.x * 2048 + tid * 8;
    int vals[8];
    int tsum = 0;
#pragma unroll
    for (int j = 0; j < 8; j++) {
        int v = (tbase + j < RTOT) ? g_cnt[tbase + j] : 0;
        vals[j] = tsum;
        tsum += v;
    }
    s[tid] = tsum;
    __syncthreads();
    for (int off = 1; off < 256; off <<= 1) {
        int t = (tid >= off) ? s[tid - off] : 0;
        __syncthreads();
        s[tid] += t;
        __syncthreads();
    }
    const int texcl = (tid > 0) ? s[tid - 1] : 0;
    if (tid == 255) g_bsum[blockIdx.x] = s[255];
#pragma unroll
    for (int j = 0; j < 8; j++)
        if (tbase + j < RTOT) g_rowptr[tbase + j] = vals[j] + texcl;
}

__global__ void __launch_bounds__(512) scan2_kernel(int nb)
{
    __shared__ int s[512];
    const int tid = threadIdx.x;
    s[tid] = (tid < nb) ? g_bsum[tid] : 0;
    __syncthreads();
    for (int off = 1; off < 512; off <<= 1) {
        int t = (tid >= off) ? s[tid - off] : 0;
        __syncthreads();
        s[tid] += t;
        __syncthreads();
    }
    g_bsum[tid] = (tid > 0) ? s[tid - 1] : 0;
}

__global__ void scan3_kernel()
{
    const int i = blockIdx.x * blockDim.x + threadIdx.x;
    if (i < RTOT) {
        int v = g_rowptr[i] + g_bsum[i >> 11];
        g_rowptr[i] = v;
        g_cursor[i] = v;
    } else if (i == RTOT) {
        g_rowptr[RTOT] = TOTE;
    }
}

__global__ void fill_kernel(const int* __restrict__ src_idx,
                            const int* __restrict__ dst_idx)
{
    const int e = blockIdx.y;
    const int i = blockIdx.x * blockDim.x + threadIdx.x;
    if (i >= E) return;
    const int d = dst_idx[(size_t)e * E + i];
    const int s = src_idx[(size_t)e * E + i];
    const int pos = atomicAdd(&g_cursor[c_ROFF[e] + d], 1);
    g_ebuf[pos] = c_OFF[c_ST[e]] + s;
}

// ---------------------------------------------------------------------------
// L1 fused aggregate+combine; gather loop 2-way unrolled (2x MLP).
// Accumulation order preserved (e0 then e1 sequential) -> bit-identical.
// ---------------------------------------------------------------------------
__global__ void __launch_bounds__(256) l1_fused_kernel(
    __half* __restrict__ out1, const __half* __restrict__ wroot,
    int tOff, int Nn, int roff0, int roff1, int roff2, int R)
{
    __shared__ float smb[8][128];
    __shared__ float sma[8][256];

    const int warp = threadIdx.x >> 5;
    const int lane = threadIdx.x & 31;
    const int n = blockIdx.x * 8 + warp;
    if (n >= Nn) return;
    const int c4 = lane * 4;
    const int h  = lane >> 2;

    {
        const uint2 raw = *(const uint2*)(g_bases + (size_t)(tOff + n) * 128 + c4);
        const float2 lo = __half22float2(*(const __half2*)&raw.x);
        const float2 hi = __half22float2(*(const __half2*)&raw.y);
        smb[warp][c4 + 0] = lo.x; smb[warp][c4 + 1] = lo.y;
        smb[warp][c4 + 2] = hi.x; smb[warp][c4 + 3] = hi.y;
    }
    __syncwarp();

    float val[8];
    {
        const uint2 raw = *(const uint2*)(wroot + (size_t)n * 32 + h * 4);
        const float2 w01 = __half22float2(*(const __half2*)&raw.x);
        const float2 w23 = __half22float2(*(const __half2*)&raw.y);
#pragma unroll
        for (int j = 0; j < 8; j++) {
            const int dd = (lane * 8 + j) & 31;
            val[j] = w01.x * smb[warp][dd] + w01.y * smb[warp][32 + dd] +
                     w23.x * smb[warp][64 + dd] + w23.y * smb[warp][96 + dd];
        }
    }

    const int roffs[3] = {roff0, roff1, roff2};
    for (int r = 0; r < R; r++) {
        const int g = roffs[r] + n;
        const int rs = g_rowptr[g];
        const int re = g_rowptr[g + 1];
        const int ct = re - rs;
        float4 s4 = make_float4(0.f, 0.f, 0.f, 0.f);
        float4 m4 = make_float4(-INFINITY, -INFINITY, -INFINITY, -INFINITY);
        int k = rs;
        for (; k + 1 < re; k += 2) {
            const int i0 = g_ebuf[k];
            const int i1 = g_ebuf[k + 1];
            const uint2 r0 = *(const uint2*)(g_bases + (size_t)i0 * 128 + c4);
            const uint2 r1 = *(const uint2*)(g_bases + (size_t)i1 * 128 + c4);
            const float2 a0 = __half22float2(*(const __half2*)&r0.x);
            const float2 a1 = __half22float2(*(const __half2*)&r0.y);
            s4.x += a0.x; s4.y += a0.y; s4.z += a1.x; s4.w += a1.y;
            m4.x = fmaxf(m4.x, a0.x); m4.y = fmaxf(m4.y, a0.y);
            m4.z = fmaxf(m4.z, a1.x); m4.w = fmaxf(m4.w, a1.y);
            const float2 b0 = __half22float2(*(const __half2*)&r1.x);
            const float2 b1 = __half22float2(*(const __half2*)&r1.y);
            s4.x += b0.x; s4.y += b0.y; s4.z += b1.x; s4.w += b1.y;
            m4.x = fmaxf(m4.x, b0.x); m4.y = fmaxf(m4.y, b0.y);
            m4.z = fmaxf(m4.z, b1.x); m4.w = fmaxf(m4.w, b1.y);
        }
        if (k < re) {
            const int i0 = g_ebuf[k];
            const uint2 r0 = *(const uint2*)(g_bases + (size_t)i0 * 128 + c4);
            const float2 a0 = __half22float2(*(const __half2*)&r0.x);
            const float2 a1 = __half22float2(*(const __half2*)&r0.y);
            s4.x += a0.x; s4.y += a0.y; s4.z += a1.x; s4.w += a1.y;
            m4.x = fmaxf(m4.x, a0.x); m4.y = fmaxf(m4.y, a0.y);
            m4.z = fmaxf(m4.z, a1.x); m4.w = fmaxf(m4.w, a1.y);
        }
        const float inv = 1.f / (float)(ct > 1 ? ct : 1);
        s4.x *= inv; s4.y *= inv; s4.z *= inv; s4.w *= inv;
        if (ct == 0) m4 = make_float4(0.f, 0.f, 0.f, 0.f);
        *(float4*)&sma[warp][c4]       = s4;
        *(float4*)&sma[warp][128 + c4] = m4;
        __syncwarp();
        const uint4 raw = *(const uint4*)(g_wrel + (size_t)g * 64 + h * 8);
        const float2 w01 = __half22float2(*(const __half2*)&raw.x);
        const float2 w23 = __half22float2(*(const __half2*)&raw.y);
        const float2 w45 = __half22float2(*(const __half2*)&raw.z);
        const float2 w67 = __half22float2(*(const __half2*)&raw.w);
        const float wv[8] = {w01.x, w01.y, w23.x, w23.y, w45.x, w45.y, w67.x, w67.y};
#pragma unroll
        for (int j = 0; j < 8; j++) {
            const int dd = (lane * 8 + j) & 31;
#pragma unroll
            for (int b = 0; b < 8; b++)
                val[j] += wv[b] * sma[warp][b * 32 + dd];
        }
        __syncwarp();
    }

    union { __half2 h[4]; uint4 u; } pk;
#pragma unroll
    for (int q = 0; q < 4; q++)
        pk.h[q] = __floats2half2_rn(fmaxf(val[2 * q], 0.f), fmaxf(val[2 * q + 1], 0.f));
    *(uint4*)(out1 + (size_t)n * 256 + lane * 8) = pk.u;
}

// ---------------------------------------------------------------------------
// L2 aggregation; gather loop 2-way unrolled (2x MLP), order preserved.
// ---------------------------------------------------------------------------
__global__ void __launch_bounds__(256) l2_agg_kernel()
{
    const int warp = threadIdx.x >> 5;
    const int lane = threadIdx.x & 31;
    const int g = blockIdx.x * 8 + warp;
    if (g >= RTOT) return;
    const int c8 = lane * 8;
    const int rs = g_rowptr[g];
    const int re = g_rowptr[g + 1];
    const int ct = re - rs;
    float a[8];
#pragma unroll
    for (int j = 0; j < 8; j++) a[j] = 0.f;
    int k = rs;
    for (; k + 1 < re; k += 2) {
        const int i0 = g_ebuf[k];
        const int i1 = g_ebuf[k + 1];
        const uint4 r0 = *(const uint4*)(g_out1 + (size_t)i0 * 256 + c8);
        const uint4 r1 = *(const uint4*)(g_out1 + (size_t)i1 * 256 + c8);
        {
            const float2 v0 = __half22float2(*(const __half2*)&r0.x);
            const float2 v1 = __half22float2(*(const __half2*)&r0.y);
            const float2 v2 = __half22float2(*(const __half2*)&r0.z);
            const float2 v3 = __half22float2(*(const __half2*)&r0.w);
            a[0] += v0.x; a[1] += v0.y; a[2] += v1.x; a[3] += v1.y;
            a[4] += v2.x; a[5] += v2.y; a[6] += v3.x; a[7] += v3.y;
        }
        {
            const float2 v0 = __half22float2(*(const __half2*)&r1.x);
            const float2 v1 = __half22float2(*(const __half2*)&r1.y);
            const float2 v2 = __half22float2(*(const __half2*)&r1.z);
            const float2 v3 = __half22float2(*(const __half2*)&r1.w);
            a[0] += v0.x; a[1] += v0.y; a[2] += v1.x; a[3] += v1.y;
            a[4] += v2.x; a[5] += v2.y; a[6] += v3.x; a[7] += v3.y;
        }
    }
    if (k < re) {
        const int i0 = g_ebuf[k];
        const uint4 r0 = *(const uint4*)(g_out1 + (size_t)i0 * 256 + c8);
        const float2 v0 = __half22float2(*(const __half2*)&r0.x);
        const float2 v1 = __half22float2(*(const __half2*)&r0.y);
        const float2 v2 = __half22float2(*(const __half2*)&r0.z);
        const float2 v3 = __half22float2(*(const __half2*)&r0.w);
        a[0] += v0.x; a[1] += v0.y; a[2] += v1.x; a[3] += v1.y;
        a[4] += v2.x; a[5] += v2.y; a[6] += v3.x; a[7] += v3.y;
    }
    const float inv = 1.f / (float)(ct > 1 ? ct : 1);
    union { __half2 h[4]; uint4 u; } pk;
#pragma unroll
    for (int q = 0; q < 4; q++)
        pk.h[q] = __floats2half2_rn(a[2 * q] * inv, a[2 * q + 1] * inv);
    *(uint4*)(g_sum2 + (size_t)g * 256 + c8) = pk.u;
}

// ---------------------------------------------------------------------------
// host
// ---------------------------------------------------------------------------
extern "C" void kernel_launch(void* const* d_in, const int* in_sizes, int n_in,
                              void* d_out, int out_size)
{
    const float* x_paper    = (const float*)d_in[0];
    const float* emb_author = (const float*)d_in[1];
    const float* emb_fos    = (const float*)d_in[2];
    const float* emb_inst   = (const float*)d_in[3];
    const float* bases_w1   = (const float*)d_in[4];
    const float* rel_w1     = (const float*)d_in[5];
    const float* rel_b1     = (const float*)d_in[6];
    const float* root_w1    = (const float*)d_in[7];
    const float* root_b1    = (const float*)d_in[8];
    const float* rel_w2     = (const float*)d_in[9];
    const float* root_w2    = (const float*)d_in[10];
    const float* root_b2    = (const float*)d_in[11];
    const int*   src_idx    = (const int*)d_in[12];
    const int*   dst_idx    = (const int*)d_in[13];
    float* out = (float*)d_out;

    static const int NUMSh[4] = {200000, 30000, 5000, 150000};
    static const int OFFh[4]  = {0, 200000, 230000, 235000};
    static const int DT[7] = {2, 0, 3, 0, 3, 1, 3};
    static const int ROFFh[7] = {0, 5000, 205000, 355000, 555000, 705000, 735000};

    __half *xh_p, *bases_p, *out1_p, *wroot_p, *wrel_p, *sum2_p, *w1p_p, *w2p_p;
    float* b1p_p;
    int* cnt_p;
    cudaGetSymbolAddress((void**)&xh_p,    g_xh);
    cudaGetSymbolAddress((void**)&bases_p, g_bases);
    cudaGetSymbolAddress((void**)&out1_p,  g_out1);
    cudaGetSymbolAddress((void**)&wroot_p, g_wroot);
    cudaGetSymbolAddress((void**)&wrel_p,  g_wrel);
    cudaGetSymbolAddress((void**)&sum2_p,  g_sum2);
    cudaGetSymbolAddress((void**)&w1p_p,   g_w1p);
    cudaGetSymbolAddress((void**)&b1p_p,   g_b1p);
    cudaGetSymbolAddress((void**)&w2p_p,   g_w2p);
    cudaGetSymbolAddress((void**)&cnt_p,   g_cnt);

    const float* xs[4] = {emb_author, emb_fos, emb_inst, x_paper};

    // ---- CSR build ----
    cudaMemsetAsync(cnt_p, 0, (size_t)RTOT * sizeof(int));
    {
        dim3 grid((E + 255) / 256, 7);
        count_kernel<<<grid, 256>>>(dst_idx);
    }
    scan1_kernel<<<(RTOT + 2047) / 2048, 256>>>();
    scan2_kernel<<<1, 512>>>((RTOT + 2047) / 2048);
    scan3_kernel<<<(RTOT + 1 + 255) / 256, 256>>>();
    {
        dim3 grid((E + 255) / 256, 7);
        fill_kernel<<<grid, 256>>>(src_idx, dst_idx);
    }

    // ---- prep ----
    for (int t = 0; t < 4; t++) {
        const int n = NUMSh[t] * 128;
        cvt_half<<<(n + 255) / 256, 256>>>(xs[t], xh_p + (size_t)OFFh[t] * 128, n);
    }
    int relsOf[4][3], Rof[4];
    for (int t = 0; t < 4; t++) {
        Rof[t] = 0;
        for (int e = 0; e < 7; e++)
            if (DT[e] == t) relsOf[t][Rof[t]++] = e;
        for (int r = Rof[t]; r < 3; r++) relsOf[t][r] = relsOf[t][0];
    }
    for (int t = 0; t < 4; t++) {
        pack_w1<<<(128 * NPAD + 255) / 256, 256>>>(
            bases_w1, root_w1, rel_w1, root_b1, rel_b1,
            w1p_p + (size_t)t * 128 * NPAD, b1p_p + (size_t)t * NPAD,
            t, Rof[t], relsOf[t][0], relsOf[t][1], relsOf[t][2]);
        const int nseg = 1 + Rof[t];
        pack_w2<<<(nseg * 256 * NPAD + 255) / 256, 256>>>(
            root_w2, rel_w2, w2p_p + (size_t)t * 1024 * NPAD,
            t, nseg, relsOf[t][0], relsOf[t][1], relsOf[t][2]);
    }

    // ---- layer-1 merged GEMM per type ----
    for (int t = 0; t < 4; t++) {
        const int Ncols = 160 + 64 * Rof[t];
        const __half* A = xh_p + (size_t)OFFh[t] * 128;
        dim3 grid((Ncols + 63) / 64, (NUMSh[t] + 127) / 128);
        hgemm_h<<<grid, 256>>>(
            A, A, A, A, w1p_p + (size_t)t * 128 * NPAD, b1p_p + (size_t)t * NPAD,
            out, NUMSh[t], 128, 16, 4, 1,
            OFFh[t], ROFFh[relsOf[t][0]], ROFFh[relsOf[t][1]], ROFFh[relsOf[t][2]],
            Ncols);
    }

    // ---- layer-1 fused aggregate+combine ----
    for (int t = 0; t < 4; t++) {
        l1_fused_kernel<<<(NUMSh[t] + 7) / 8, 256>>>(
            out1_p + (size_t)OFFh[t] * 256, wroot_p + (size_t)OFFh[t] * 32,
            OFFh[t], NUMSh[t],
            ROFFh[relsOf[t][0]], ROFFh[relsOf[t][1]], ROFFh[relsOf[t][2]], Rof[t]);
    }

    // ---- layer-2 aggregation ----
    l2_agg_kernel<<<(RTOT + 7) / 8, 256>>>();

    // ---- layer-2 multi-segment GEMM per type ----
    for (int t = 0; t < 4; t++) {
        const __half* A[4];
        A[0] = out1_p + (size_t)OFFh[t] * 256;
        int nseg = 1;
        for (int r = 0; r < Rof[t]; r++)
            A[nseg++] = sum2_p + (size_t)ROFFh[relsOf[t][r]] * 256;
        for (int s2 = nseg; s2 < 4; s2++) A[s2] = A[0];
        dim3 grid(6, (NUMSh[t] + 127) / 128);
        hgemm_h<<<grid, 256>>>(
            A[0], A[1], A[2], A[3], w2p_p + (size_t)t * 1024 * NPAD,
            root_b2 + (size_t)t * 349,
            out + (size_t)OFFh[t] * 349, NUMSh[t], 256, 3, nseg * 8, 0,
            0, 0, 0, 0, 349);
    }
}

// round 16
// speedup vs baseline: 1.8436x; 1.0603x over previous
#include <cuda_runtime.h>
#include <cuda_fp16.h>
#include <math.h>
#include <stdint.h>

// ---------------------------------------------------------------------------
// REGC hetero-GNN. fp16 HMMA GEMMs (R11-frozen mainloop, merged per-type
// launches), CSR aggregation with 4-way unrolled gathers, fp16 intermediates.
// ---------------------------------------------------------------------------

#define E     400000
#define RTOT  885000
#define TOTE  2800000
#define NPAD  384

__device__ __half g_xh   [(size_t)385000 * 128];
__device__ __half g_bases[(size_t)385000 * 128];
__device__ __half g_out1 [(size_t)385000 * 256];   // post-ReLU
__device__ __half g_wroot[(size_t)385000 * 32];
__device__ __half g_wrel [(size_t)RTOT * 64];
__device__ __half g_sum2 [(size_t)RTOT * 256];
__device__ __half g_w1p  [4][(size_t)128 * NPAD];
__device__ float  g_b1p  [4][NPAD];
__device__ __half g_w2p  [4][(size_t)1024 * NPAD];
__device__ int    g_cnt   [RTOT];
__device__ int    g_rowptr[RTOT + 1];
__device__ int    g_cursor[RTOT];
__device__ int    g_ebuf  [TOTE];
__device__ int    g_bsum  [512];

__device__ __constant__ int c_ST[7]   = {0, 2, 0, 3, 3, 3, 1};
__device__ __constant__ int c_OFF[4]  = {0, 200000, 230000, 235000};
__device__ __constant__ int c_ROFF[7] = {0, 5000, 205000, 355000, 555000, 705000, 735000};

// ---------------------------------------------------------------------------
// merged-GEMM per-type parameter block (passed by value)
// ---------------------------------------------------------------------------
struct GP {
    const __half* A[4][4];   // [type][segment]
    const __half* Bp[4];
    const float*  bias[4];
    float* Cf;
    int mstart[4];           // starting m-tile index per type (cumulative)
    int M[4], nodeOff[4], ro0[4], ro1[4], ro2[4], Ncols[4], nit[4];
};

// ---------------------------------------------------------------------------
// fp16 GEMM (R11-frozen body): BM=128 BN=64 BK=32, 256 thr, warp tile 32x32.
// Register prefetch, two syncs/iter — R12/R13 variants both regressed.
// mode 0: C f32 = acc + bias (row stride 349, scalar stores; 349 odd)
// mode 1: scatter cols [0,128)->g_bases, [128,160)->g_wroot, [160,..)->g_wrel
// ---------------------------------------------------------------------------
__global__ void __launch_bounds__(256) hgemm_multi(
    GP p, int aStride, int segShift, int mode)
{
    const int y = blockIdx.y;
    const int t = (y >= p.mstart[3]) ? 3 : (y >= p.mstart[2]) ? 2 :
                  (y >= p.mstart[1]) ? 1 : 0;
    const int M = p.M[t];
    const int Ncols = p.Ncols[t];
    const int nit = p.nit[t];
    const int n0 = blockIdx.x * 64;
    if (n0 >= Ncols) return;              // whole block exits (pre-sync)
    const int m0 = (y - p.mstart[t]) * 128;

    __shared__ __align__(16) __half As[128][40];
    __shared__ __align__(16) __half Bs[32][72];

    const __half* const* Aseg = p.A[t];
    const __half* Bp = p.Bp[t];
    const float* bias = p.bias[t];
    const int nodeOff = p.nodeOff[t];
    const int ro0 = p.ro0[t], ro1 = p.ro1[t], ro2 = p.ro2[t];

    const int tid  = threadIdx.x;
    const int lane = tid & 31;
    const int warp = tid >> 5;
    const int wm = (warp & 3) * 32;
    const int wn = (warp >> 2) * 32;

    const int am = tid >> 1;
    const int ak = (tid & 1) * 16;
    const int bk = tid >> 3;
    const int bn = (tid & 7) * 8;

    uint4 pa0, pa1, pb;

    auto load_g = [&](int it) {
        const int seg = it >> segShift;
        const int k0 = (it - (seg << segShift)) * 32;
        const int gm = m0 + am;
        const __half* ap = Aseg[seg] + (size_t)(gm < M ? gm : 0) * aStride + k0 + ak;
        pa0 = *(const uint4*)ap;
        pa1 = *(const uint4*)(ap + 8);
        pb  = *(const uint4*)(Bp + (size_t)(it * 32 + bk) * NPAD + n0 + bn);
    };
    auto store_s = [&]() {
        *(uint4*)&As[am][ak]     = pa0;
        *(uint4*)&As[am][ak + 8] = pa1;
        *(uint4*)&Bs[bk][bn]     = pb;
    };

    float acc[2][4][4];
#pragma unroll
    for (int mi = 0; mi < 2; mi++)
#pragma unroll
        for (int nj = 0; nj < 4; nj++)
#pragma unroll
            for (int r = 0; r < 4; r++) acc[mi][nj][r] = 0.f;

    const uint32_t sA = (uint32_t)__cvta_generic_to_shared(&As[0][0]);
    const uint32_t sB = (uint32_t)__cvta_generic_to_shared(&Bs[0][0]);
    const uint32_t aAddr0 = sA + (uint32_t)((wm + (lane & 15)) * 80 + ((lane >> 4) * 8) * 2);
    const uint32_t bAddr0 = sB + (uint32_t)(((lane & 15)) * 144 + (wn + (lane >> 4) * 8) * 2);

    auto compute = [&]() {
#pragma unroll
        for (int kk = 0; kk < 2; kk++) {
            uint32_t a[2][4], b[4][2];
#pragma unroll
            for (int mi = 0; mi < 2; mi++) {
                uint32_t addr = aAddr0 + (uint32_t)(mi * 16 * 80 + kk * 16 * 2);
                asm volatile("ldmatrix.sync.aligned.m8n8.x4.shared.b16 {%0,%1,%2,%3}, [%4];"
                             : "=r"(a[mi][0]), "=r"(a[mi][1]), "=r"(a[mi][2]), "=r"(a[mi][3])
                             : "r"(addr));
            }
#pragma unroll
            for (int njp = 0; njp < 2; njp++) {
                uint32_t addr = bAddr0 + (uint32_t)(kk * 16 * 144 + njp * 16 * 2);
                asm volatile("ldmatrix.sync.aligned.m8n8.x4.trans.shared.b16 {%0,%1,%2,%3}, [%4];"
                             : "=r"(b[njp * 2][0]), "=r"(b[njp * 2][1]),
                               "=r"(b[njp * 2 + 1][0]), "=r"(b[njp * 2 + 1][1])
                             : "r"(addr));
            }
#pragma unroll
            for (int mi = 0; mi < 2; mi++)
#pragma unroll
                for (int nj = 0; nj < 4; nj++) {
                    asm volatile(
                        "mma.sync.aligned.m16n8k16.row.col.f32.f16.f16.f32 "
                        "{%0,%1,%2,%3}, {%4,%5,%6,%7}, {%8,%9}, {%0,%1,%2,%3};"
                        : "+f"(acc[mi][nj][0]), "+f"(acc[mi][nj][1]),
                          "+f"(acc[mi][nj][2]), "+f"(acc[mi][nj][3])
                        : "r"(a[mi][0]), "r"(a[mi][1]), "r"(a[mi][2]), "r"(a[mi][3]),
                          "r"(b[nj][0]), "r"(b[nj][1]));
                }
        }
    };

    load_g(0);
    store_s();
    __syncthreads();
    for (int it = 1; it < nit; it++) {
        load_g(it);
        compute();
        __syncthreads();
        store_s();
        __syncthreads();
    }
    compute();

    // ---- epilogue ----
#pragma unroll
    for (int mi = 0; mi < 2; mi++)
#pragma unroll
        for (int nj = 0; nj < 4; nj++)
#pragma unroll
            for (int rp = 0; rp < 2; rp++) {
                const int row = m0 + wm + mi * 16 + (lane >> 2) + rp * 8;
                const int col = n0 + wn + nj * 8 + (lane & 3) * 2;
                if (row >= M || col >= Ncols) continue;
                const bool pair = (col + 1 < Ncols);
                const float v0 = acc[mi][nj][rp * 2 + 0] + bias[col];
                const float v1 = acc[mi][nj][rp * 2 + 1] + bias[pair ? col + 1 : col];
                if (mode == 0) {
                    float* pc = p.Cf + (size_t)(nodeOff + row) * 349 + col;
                    pc[0] = v0;
                    if (pair) pc[1] = v1;
                } else {
                    const __half2 h2 = __floats2half2_rn(v0, v1);
                    if (col < 128) {
                        *(__half2*)(g_bases + (size_t)(nodeOff + row) * 128 + col) = h2;
                    } else if (col < 160) {
                        *(__half2*)(g_wroot + (size_t)(nodeOff + row) * 32 + (col - 128)) = h2;
                    } else {
                        const int cc = col - 160;
                        const int rr = cc >> 6;
                        const int ro = (rr == 0) ? ro0 : ((rr == 1) ? ro1 : ro2);
                        *(__half2*)(g_wrel + (size_t)(ro + row) * 64 + (cc & 63)) = h2;
                    }
                }
            }
}

// ---------------------------------------------------------------------------
// prep: all four feature tensors -> fp16, one launch, float4 vectorized
// ---------------------------------------------------------------------------
__global__ void cvt_all(const float* __restrict__ x0, const float* __restrict__ x1,
                        const float* __restrict__ x2, const float* __restrict__ x3)
{
    const long long q = (long long)blockIdx.x * blockDim.x + threadIdx.x;  // float4 id
    const long long i = q * 4;
    if (i >= 49280000LL) return;
    const float* src;
    long long base;
    if (i < 25600000LL)      { src = x0; base = 0; }
    else if (i < 29440000LL) { src = x1; base = 25600000LL; }
    else if (i < 30080000LL) { src = x2; base = 29440000LL; }
    else                     { src = x3; base = 30080000LL; }
    const float4 v = *(const float4*)(src + (i - base));
    union { __half2 h[2]; uint2 u; } pk;
    pk.h[0] = __floats2half2_rn(v.x, v.y);
    pk.h[1] = __floats2half2_rn(v.z, v.w);
    *(uint2*)(g_xh + i) = pk.u;
}

struct PackT { int R[4], e0[4], e1[4], e2[4]; };

__global__ void pack_w1_all(const float* __restrict__ bases_w1,
                            const float* __restrict__ root_w1,
                            const float* __restrict__ rel_w1,
                            const float* __restrict__ root_b1,
                            const float* __restrict__ rel_b1, PackT pt)
{
    const int t = blockIdx.y;
    const int i = blockIdx.x * blockDim.x + threadIdx.x;
    if (i >= 128 * NPAD) return;
    const int k = i / NPAD, n = i % NPAD;
    float v = 0.f, b = 0.f;
    if (n < 128) {
        v = bases_w1[k * 128 + n];
    } else if (n < 160) {
        v = root_w1[((size_t)t * 32 + (n - 128)) * 128 + k];
        b = root_b1[t * 32 + (n - 128)];
    } else {
        const int cc = n - 160;
        const int r = cc >> 6;
        if (r < pt.R[t]) {
            const int e = (r == 0) ? pt.e0[t] : ((r == 1) ? pt.e1[t] : pt.e2[t]);
            v = rel_w1[((size_t)e * 64 + (cc & 63)) * 128 + k];
            b = rel_b1[e * 64 + (cc & 63)];
        }
    }
    g_w1p[t][(size_t)k * NPAD + n] = __float2half_rn(v);
    if (k == 0) g_b1p[t][n] = b;
}

__global__ void pack_w2_all(const float* __restrict__ root_w2,
                            const float* __restrict__ rel_w2, PackT pt)
{
    const int t = blockIdx.y;
    const int i = blockIdx.x * blockDim.x + threadIdx.x;
    if (i >= 4 * 256 * NPAD) return;
    const int kg = i / NPAD, n = i % NPAD;
    const int seg = kg >> 8, k = kg & 255;
    if (seg > pt.R[t]) return;            // segments beyond nseg are never read
    float v = 0.f;
    if (n < 349) {
        if (seg == 0) v = root_w2[((size_t)t * 349 + n) * 256 + k];
        else {
            const int e = (seg == 1) ? pt.e0[t] : ((seg == 2) ? pt.e1[t] : pt.e2[t]);
            v = rel_w2[((size_t)e * 349 + n) * 256 + k];
        }
    }
    g_w2p[t][(size_t)kg * NPAD + n] = __float2half_rn(v);
}

// ---------------------------------------------------------------------------
// CSR build (validated)
// ---------------------------------------------------------------------------
__global__ void count_kernel(const int* __restrict__ dst_idx)
{
    const int e = blockIdx.y;
    const int i = blockIdx.x * blockDim.x + threadIdx.x;
    if (i >= E) return;
    atomicAdd(&g_cnt[c_ROFF[e] + dst_idx[(size_t)e * E + i]], 1);
}

__global__ void __launch_bounds__(256) scan1_kernel()
{
    __shared__ int s[256];
    const int tid = threadIdx.x;
    const int tbase = blockIdx.x * 2048 + tid * 8;
    int vals[8];
    int tsum = 0;
#pragma unroll
    for (int j = 0; j < 8; j++) {
        int v = (tbase + j < RTOT) ? g_cnt[tbase + j] : 0;
        vals[j] = tsum;
        tsum += v;
    }
    s[tid] = tsum;
    __syncthreads();
    for (int off = 1; off < 256; off <<= 1) {
        int t = (tid >= off) ? s[tid - off] : 0;
        __syncthreads();
        s[tid] += t;
        __syncthreads();
    }
    const int texcl = (tid > 0) ? s[tid - 1] : 0;
    if (tid == 255) g_bsum[blockIdx.x] = s[255];
#pragma unroll
    for (int j = 0; j < 8; j++)
        if (tbase + j < RTOT) g_rowptr[tbase + j] = vals[j] + texcl;
}

__global__ void __launch_bounds__(512) scan2_kernel(int nb)
{
    __shared__ int s[512];
    const int tid = threadIdx.x;
    s[tid] = (tid < nb) ? g_bsum[tid] : 0;
    __syncthreads();
    for (int off = 1; off < 512; off <<= 1) {
        int t = (tid >= off) ? s[tid - off] : 0;
        __syncthreads();
        s[tid] += t;
        __syncthreads();
    }
    g_bsum[tid] = (tid > 0) ? s[tid - 1] : 0;
}

__global__ void scan3_kernel()
{
    const int i = blockIdx.x * blockDim.x + threadIdx.x;
    if (i < RTOT) {
        int v = g_rowptr[i] + g_bsum[i >> 11];
        g_rowptr[i] = v;
        g_cursor[i] = v;
    } else if (i == RTOT) {
        g_rowptr[RTOT] = TOTE;
    }
}

__global__ void fill_kernel(const int* __restrict__ src_idx,
                            const int* __restrict__ dst_idx)
{
    const int e = blockIdx.y;
    const int i = blockIdx.x * blockDim.x + threadIdx.x;
    if (i >= E) return;
    const int d = dst_idx[(size_t)e * E + i];
    const int s = src_idx[(size_t)e * E + i];
    const int pos = atomicAdd(&g_cursor[c_ROFF[e] + d], 1);
    g_ebuf[pos] = c_OFF[c_ST[e]] + s;
}

// ---------------------------------------------------------------------------
// L1 fused aggregate+combine — single launch across all types.
// Gather loop 4-way unrolled (sequential adds -> bit-identical).
// ---------------------------------------------------------------------------
struct L1F { int bbase[4], Nn[4], tOff[4], ro0[4], ro1[4], ro2[4], R[4]; };

__global__ void __launch_bounds__(256) l1_fused_all(L1F p)
{
    __shared__ float smb[8][128];
    __shared__ float sma[8][256];

    const int blk = blockIdx.x;
    const int t = (blk >= p.bbase[3]) ? 3 : (blk >= p.bbase[2]) ? 2 :
                  (blk >= p.bbase[1]) ? 1 : 0;
    const int warp = threadIdx.x >> 5;
    const int lane = threadIdx.x & 31;
    const int n = (blk - p.bbase[t]) * 8 + warp;
    if (n >= p.Nn[t]) return;
    const int tOff = p.tOff[t];
    const int R = p.R[t];
    const int c4 = lane * 4;
    const int h  = lane >> 2;

    {
        const uint2 raw = *(const uint2*)(g_bases + (size_t)(tOff + n) * 128 + c4);
        const float2 lo = __half22float2(*(const __half2*)&raw.x);
        const float2 hi = __half22float2(*(const __half2*)&raw.y);
        smb[warp][c4 + 0] = lo.x; smb[warp][c4 + 1] = lo.y;
        smb[warp][c4 + 2] = hi.x; smb[warp][c4 + 3] = hi.y;
    }
    __syncwarp();

    float val[8];
    {
        const uint2 raw = *(const uint2*)(g_wroot + (size_t)(tOff + n) * 32 + h * 4);
        const float2 w01 = __half22float2(*(const __half2*)&raw.x);
        const float2 w23 = __half22float2(*(const __half2*)&raw.y);
#pragma unroll
        for (int j = 0; j < 8; j++) {
            const int dd = (lane * 8 + j) & 31;
            val[j] = w01.x * smb[warp][dd] + w01.y * smb[warp][32 + dd] +
                     w23.x * smb[warp][64 + dd] + w23.y * smb[warp][96 + dd];
        }
    }

    const int roffs[3] = {p.ro0[t], p.ro1[t], p.ro2[t]};
    for (int r = 0; r < R; r++) {
        const int g = roffs[r] + n;
        const int rs = g_rowptr[g];
        const int re = g_rowptr[g + 1];
        const int ct = re - rs;
        float4 s4 = make_float4(0.f, 0.f, 0.f, 0.f);
        float4 m4 = make_float4(-INFINITY, -INFINITY, -INFINITY, -INFINITY);
        int k = rs;
        for (; k + 3 < re; k += 4) {
            const int i0 = g_ebuf[k], i1 = g_ebuf[k + 1];
            const int i2 = g_ebuf[k + 2], i3 = g_ebuf[k + 3];
            const uint2 r0 = *(const uint2*)(g_bases + (size_t)i0 * 128 + c4);
            const uint2 r1 = *(const uint2*)(g_bases + (size_t)i1 * 128 + c4);
            const uint2 r2 = *(const uint2*)(g_bases + (size_t)i2 * 128 + c4);
            const uint2 r3 = *(const uint2*)(g_bases + (size_t)i3 * 128 + c4);
            const uint2 rr[4] = {r0, r1, r2, r3};
#pragma unroll
            for (int u = 0; u < 4; u++) {
                const float2 a0 = __half22float2(*(const __half2*)&rr[u].x);
                const float2 a1 = __half22float2(*(const __half2*)&rr[u].y);
                s4.x += a0.x; s4.y += a0.y; s4.z += a1.x; s4.w += a1.y;
                m4.x = fmaxf(m4.x, a0.x); m4.y = fmaxf(m4.y, a0.y);
                m4.z = fmaxf(m4.z, a1.x); m4.w = fmaxf(m4.w, a1.y);
            }
        }
        for (; k + 1 < re; k += 2) {
            const int i0 = g_ebuf[k], i1 = g_ebuf[k + 1];
            const uint2 r0 = *(const uint2*)(g_bases + (size_t)i0 * 128 + c4);
            const uint2 r1 = *(const uint2*)(g_bases + (size_t)i1 * 128 + c4);
            const uint2 rr[2] = {r0, r1};
#pragma unroll
            for (int u = 0; u < 2; u++) {
                const float2 a0 = __half22float2(*(const __half2*)&rr[u].x);
                const float2 a1 = __half22float2(*(const __half2*)&rr[u].y);
                s4.x += a0.x; s4.y += a0.y; s4.z += a1.x; s4.w += a1.y;
                m4.x = fmaxf(m4.x, a0.x); m4.y = fmaxf(m4.y, a0.y);
                m4.z = fmaxf(m4.z, a1.x); m4.w = fmaxf(m4.w, a1.y);
            }
        }
        if (k < re) {
            const uint2 r0 = *(const uint2*)(g_bases + (size_t)g_ebuf[k] * 128 + c4);
            const float2 a0 = __half22float2(*(const __half2*)&r0.x);
            const float2 a1 = __half22float2(*(const __half2*)&r0.y);
            s4.x += a0.x; s4.y += a0.y; s4.z += a1.x; s4.w += a1.y;
            m4.x = fmaxf(m4.x, a0.x); m4.y = fmaxf(m4.y, a0.y);
            m4.z = fmaxf(m4.z, a1.x); m4.w = fmaxf(m4.w, a1.y);
        }
        const float inv = 1.f / (float)(ct > 1 ? ct : 1);
        s4.x *= inv; s4.y *= inv; s4.z *= inv; s4.w *= inv;
        if (ct == 0) m4 = make_float4(0.f, 0.f, 0.f, 0.f);
        *(float4*)&sma[warp][c4]       = s4;
        *(float4*)&sma[warp][128 + c4] = m4;
        __syncwarp();
        const uint4 raw = *(const uint4*)(g_wrel + (size_t)g * 64 + h * 8);
        const float2 w01 = __half22float2(*(const __half2*)&raw.x);
        const float2 w23 = __half22float2(*(const __half2*)&raw.y);
        const float2 w45 = __half22float2(*(const __half2*)&raw.z);
        const float2 w67 = __half22float2(*(const __half2*)&raw.w);
        const float wv[8] = {w01.x, w01.y, w23.x, w23.y, w45.x, w45.y, w67.x, w67.y};
#pragma unroll
        for (int j = 0; j < 8; j++) {
            const int dd = (lane * 8 + j) & 31;
#pragma unroll
            for (int b = 0; b < 8; b++)
                val[j] += wv[b] * sma[warp][b * 32 + dd];
        }
        __syncwarp();
    }

    union { __half2 h[4]; uint4 u; } pk;
#pragma unroll
    for (int q = 0; q < 4; q++)
        pk.h[q] = __floats2half2_rn(fmaxf(val[2 * q], 0.f), fmaxf(val[2 * q + 1], 0.f));
    *(uint4*)(g_out1 + (size_t)(tOff + n) * 256 + lane * 8) = pk.u;
}

// ---------------------------------------------------------------------------
// L2 aggregation; gather loop 4-way unrolled, sequential adds (bit-identical).
// ---------------------------------------------------------------------------
__global__ void __launch_bounds__(256) l2_agg_kernel()
{
    const int warp = threadIdx.x >> 5;
    const int lane = threadIdx.x & 31;
    const int g = blockIdx.x * 8 + warp;
    if (g >= RTOT) return;
    const int c8 = lane * 8;
    const int rs = g_rowptr[g];
    const int re = g_rowptr[g + 1];
    const int ct = re - rs;
    float a[8];
#pragma unroll
    for (int j = 0; j < 8; j++) a[j] = 0.f;
    int k = rs;
    for (; k + 3 < re; k += 4) {
        const int i0 = g_ebuf[k], i1 = g_ebuf[k + 1];
        const int i2 = g_ebuf[k + 2], i3 = g_ebuf[k + 3];
        const uint4 r0 = *(const uint4*)(g_out1 + (size_t)i0 * 256 + c8);
        const uint4 r1 = *(const uint4*)(g_out1 + (size_t)i1 * 256 + c8);
        const uint4 r2 = *(const uint4*)(g_out1 + (size_t)i2 * 256 + c8);
        const uint4 r3 = *(const uint4*)(g_out1 + (size_t)i3 * 256 + c8);
        const uint4 rr[4] = {r0, r1, r2, r3};
#pragma unroll
        for (int u = 0; u < 4; u++) {
            const float2 v0 = __half22float2(*(const __half2*)&rr[u].x);
            const float2 v1 = __half22float2(*(const __half2*)&rr[u].y);
            const float2 v2 = __half22float2(*(const __half2*)&rr[u].z);
            const float2 v3 = __half22float2(*(const __half2*)&rr[u].w);
            a[0] += v0.x; a[1] += v0.y; a[2] += v1.x; a[3] += v1.y;
            a[4] += v2.x; a[5] += v2.y; a[6] += v3.x; a[7] += v3.y;
        }
    }
    for (; k + 1 < re; k += 2) {
        const int i0 = g_ebuf[k], i1 = g_ebuf[k + 1];
        const uint4 r0 = *(const uint4*)(g_out1 + (size_t)i0 * 256 + c8);
        const uint4 r1 = *(const uint4*)(g_out1 + (size_t)i1 * 256 + c8);
        const uint4 rr[2] = {r0, r1};
#pragma unroll
        for (int u = 0; u < 2; u++) {
            const float2 v0 = __half22float2(*(const __half2*)&rr[u].x);
            const float2 v1 = __half22float2(*(const __half2*)&rr[u].y);
            const float2 v2 = __half22float2(*(const __half2*)&rr[u].z);
            const float2 v3 = __half22float2(*(const __half2*)&rr[u].w);
            a[0] += v0.x; a[1] += v0.y; a[2] += v1.x; a[3] += v1.y;
            a[4] += v2.x; a[5] += v2.y; a[6] += v3.x; a[7] += v3.y;
        }
    }
    if (k < re) {
        const uint4 r0 = *(const uint4*)(g_out1 + (size_t)g_ebuf[k] * 256 + c8);
        const float2 v0 = __half22float2(*(const __half2*)&r0.x);
        const float2 v1 = __half22float2(*(const __half2*)&r0.y);
        const float2 v2 = __half22float2(*(const __half2*)&r0.z);
        const float2 v3 = __half22float2(*(const __half2*)&r0.w);
        a[0] += v0.x; a[1] += v0.y; a[2] += v1.x; a[3] += v1.y;
        a[4] += v2.x; a[5] += v2.y; a[6] += v3.x; a[7] += v3.y;
    }
    const float inv = 1.f / (float)(ct > 1 ? ct : 1);
    union { __half2 h[4]; uint4 u; } pk;
#pragma unroll
    for (int q = 0; q < 4; q++)
        pk.h[q] = __floats2half2_rn(a[2 * q] * inv, a[2 * q + 1] * inv);
    *(uint4*)(g_sum2 + (size_t)g * 256 + c8) = pk.u;
}

// ---------------------------------------------------------------------------
// host
// ---------------------------------------------------------------------------
extern "C" void kernel_launch(void* const* d_in, const int* in_sizes, int n_in,
                              void* d_out, int out_size)
{
    const float* x_paper    = (const float*)d_in[0];
    const float* emb_author = (const float*)d_in[1];
    const float* emb_fos    = (const float*)d_in[2];
    const float* emb_inst   = (const float*)d_in[3];
    const float* bases_w1   = (const float*)d_in[4];
    const float* rel_w1     = (const float*)d_in[5];
    const float* rel_b1     = (const float*)d_in[6];
    const float* root_w1    = (const float*)d_in[7];
    const float* root_b1    = (const float*)d_in[8];
    const float* rel_w2     = (const float*)d_in[9];
    const float* root_w2    = (const float*)d_in[10];
    const float* root_b2    = (const float*)d_in[11];
    const int*   src_idx    = (const int*)d_in[12];
    const int*   dst_idx    = (const int*)d_in[13];
    float* out = (float*)d_out;

    static const int NUMSh[4] = {200000, 30000, 5000, 150000};
    static const int OFFh[4]  = {0, 200000, 230000, 235000};
    static const int DT[7] = {2, 0, 3, 0, 3, 1, 3};
    static const int ROFFh[7] = {0, 5000, 205000, 355000, 555000, 705000, 735000};

    __half *xh_p, *out1_p, *sum2_p, *w1p_p, *w2p_p;
    float* b1p_p;
    int* cnt_p;
    cudaGetSymbolAddress((void**)&xh_p,    g_xh);
    cudaGetSymbolAddress((void**)&out1_p,  g_out1);
    cudaGetSymbolAddress((void**)&sum2_p,  g_sum2);
    cudaGetSymbolAddress((void**)&w1p_p,   g_w1p);
    cudaGetSymbolAddress((void**)&b1p_p,   g_b1p);
    cudaGetSymbolAddress((void**)&w2p_p,   g_w2p);
    cudaGetSymbolAddress((void**)&cnt_p,   g_cnt);

    int relsOf[4][3], Rof[4];
    for (int t = 0; t < 4; t++) {
        Rof[t] = 0;
        for (int e = 0; e < 7; e++)
            if (DT[e] == t) relsOf[t][Rof[t]++] = e;
        for (int r = Rof[t]; r < 3; r++) relsOf[t][r] = relsOf[t][0];
    }

    // ---- CSR build ----
    cudaMemsetAsync(cnt_p, 0, (size_t)RTOT * sizeof(int));
    {
        dim3 grid((E + 255) / 256, 7);
        count_kernel<<<grid, 256>>>(dst_idx);
    }
    scan1_kernel<<<(RTOT + 2047) / 2048, 256>>>();
    scan2_kernel<<<1, 512>>>((RTOT + 2047) / 2048);
    scan3_kernel<<<(RTOT + 1 + 255) / 256, 256>>>();
    {
        dim3 grid((E + 255) / 256, 7);
        fill_kernel<<<grid, 256>>>(src_idx, dst_idx);
    }

    // ---- prep (merged launches) ----
    cvt_all<<<(49280000 / 4 + 255) / 256, 256>>>(emb_author, emb_fos, emb_inst, x_paper);
    PackT pt;
    for (int t = 0; t < 4; t++) {
        pt.R[t] = Rof[t];
        pt.e0[t] = relsOf[t][0]; pt.e1[t] = relsOf[t][1]; pt.e2[t] = relsOf[t][2];
    }
    {
        dim3 grid((128 * NPAD + 255) / 256, 4);
        pack_w1_all<<<grid, 256>>>(bases_w1, root_w1, rel_w1, root_b1, rel_b1, pt);
    }
    {
        dim3 grid((4 * 256 * NPAD + 255) / 256, 4);
        pack_w2_all<<<grid, 256>>>(root_w2, rel_w2, pt);
    }

    // ---- layer-1 merged GEMM (one launch, all types) ----
    {
        GP p;
        p.Cf = out;   // unused in mode 1
        int ms = 0;
        for (int t = 0; t < 4; t++) {
            const __half* A = xh_p + (size_t)OFFh[t] * 128;
            for (int s = 0; s < 4; s++) p.A[t][s] = A;
            p.Bp[t] = w1p_p + (size_t)t * 128 * NPAD;
            p.bias[t] = b1p_p + (size_t)t * NPAD;
            p.mstart[t] = ms;
            ms += (NUMSh[t] + 127) / 128;
            p.M[t] = NUMSh[t];
            p.nodeOff[t] = OFFh[t];
            p.ro0[t] = ROFFh[relsOf[t][0]];
            p.ro1[t] = ROFFh[relsOf[t][1]];
            p.ro2[t] = ROFFh[relsOf[t][2]];
            p.Ncols[t] = 160 + 64 * Rof[t];
            p.nit[t] = 4;
        }
        dim3 grid(6, ms);   // max Ncols 352 -> 6 tiles; blocks beyond exit early
        hgemm_multi<<<grid, 256>>>(p, 128, 16, 1);
    }

    // ---- layer-1 fused aggregate+combine (one launch) ----
    {
        L1F p;
        int bb = 0;
        for (int t = 0; t < 4; t++) {
            p.bbase[t] = bb;
            bb += (NUMSh[t] + 7) / 8;
            p.Nn[t] = NUMSh[t];
            p.tOff[t] = OFFh[t];
            p.ro0[t] = ROFFh[relsOf[t][0]];
            p.ro1[t] = ROFFh[relsOf[t][1]];
            p.ro2[t] = ROFFh[relsOf[t][2]];
            p.R[t] = Rof[t];
        }
        l1_fused_all<<<bb, 256>>>(p);
    }

    // ---- layer-2 aggregation ----
    l2_agg_kernel<<<(RTOT + 7) / 8, 256>>>();

    // ---- layer-2 merged multi-segment GEMM (one launch) ----
    {
        GP p;
        p.Cf = out;
        int ms = 0;
        for (int t = 0; t < 4; t++) {
            p.A[t][0] = out1_p + (size_t)OFFh[t] * 256;
            int nseg = 1;
            for (int r = 0; r < Rof[t]; r++)
                p.A[t][nseg++] = sum2_p + (size_t)ROFFh[relsOf[t][r]] * 256;
            for (int s = nseg; s < 4; s++) p.A[t][s] = p.A[t][0];
            p.Bp[t] = w2p_p + (size_t)t * 1024 * NPAD;
            p.bias[t] = root_b2 + (size_t)t * 349;
            p.mstart[t] = ms;
            ms += (NUMSh[t] + 127) / 128;
            p.M[t] = NUMSh[t];
            p.nodeOff[t] = OFFh[t];
            p.ro0[t] = 0; p.ro1[t] = 0; p.ro2[t] = 0;
            p.Ncols[t] = 349;
            p.nit[t] = nseg * 8;
        }
        dim3 grid(6, ms);
        hgemm_multi<<<grid, 256>>>(p, 256, 3, 0);
    }
}

// round 17
// speedup vs baseline: 1.8712x; 1.0149x over previous
#include <cuda_runtime.h>
#include <cuda_fp16.h>
#include <math.h>
#include <stdint.h>

// ---------------------------------------------------------------------------
// REGC hetero-GNN. fp16 HMMA GEMMs (R11-frozen mainloop, merged per-type
// launches), CSR aggregation (4/8-way unrolled gathers), fp16 intermediates.
// 9 launches total: misc(count+cvt+packs), scan x3, fill, gemm1, l1f, l2agg,
// gemm2.
// ---------------------------------------------------------------------------

#define E     400000
#define RTOT  885000
#define TOTE  2800000
#define NPAD  384

__device__ __half g_xh   [(size_t)385000 * 128];
__device__ __half g_bases[(size_t)385000 * 128];
__device__ __half g_out1 [(size_t)385000 * 256];   // post-ReLU
__device__ __half g_wroot[(size_t)385000 * 32];
__device__ __half g_wrel [(size_t)RTOT * 64];
__device__ __half g_sum2 [(size_t)RTOT * 256];
__device__ __half g_w1p  [4][(size_t)128 * NPAD];
__device__ float  g_b1p  [4][NPAD];
__device__ __half g_w2p  [4][(size_t)1024 * NPAD];
__device__ int    g_cnt   [RTOT];
__device__ int    g_rowptr[RTOT + 1];
__device__ int    g_cursor[RTOT];
__device__ int    g_ebuf  [TOTE];
__device__ int    g_bsum  [512];

__device__ __constant__ int c_ST[7]   = {0, 2, 0, 3, 3, 3, 1};
__device__ __constant__ int c_OFF[4]  = {0, 200000, 230000, 235000};
__device__ __constant__ int c_ROFF[7] = {0, 5000, 205000, 355000, 555000, 705000, 735000};

// ---------------------------------------------------------------------------
// merged-GEMM per-type parameter block (passed by value)
// ---------------------------------------------------------------------------
struct GP {
    const __half* A[4][4];   // [type][segment]
    const __half* Bp[4];
    const float*  bias[4];
    float* Cf;
    int mstart[4];
    int M[4], nodeOff[4], ro0[4], ro1[4], ro2[4], Ncols[4], nit[4];
};

// ---------------------------------------------------------------------------
// fp16 GEMM (R11-frozen body): BM=128 BN=64 BK=32, 256 thr, warp tile 32x32.
// Register prefetch, two syncs/iter — R12/R13 variants both regressed.
// mode 0: C f32 = acc + bias (row stride 349, scalar stores; 349 odd)
// mode 1: scatter cols [0,128)->g_bases, [128,160)->g_wroot, [160,..)->g_wrel
// ---------------------------------------------------------------------------
__global__ void __launch_bounds__(256) hgemm_multi(
    GP p, int aStride, int segShift, int mode)
{
    const int y = blockIdx.y;
    const int t = (y >= p.mstart[3]) ? 3 : (y >= p.mstart[2]) ? 2 :
                  (y >= p.mstart[1]) ? 1 : 0;
    const int M = p.M[t];
    const int Ncols = p.Ncols[t];
    const int nit = p.nit[t];
    const int n0 = blockIdx.x * 64;
    if (n0 >= Ncols) return;              // whole block exits (pre-sync)
    const int m0 = (y - p.mstart[t]) * 128;

    __shared__ __align__(16) __half As[128][40];
    __shared__ __align__(16) __half Bs[32][72];

    const __half* const* Aseg = p.A[t];
    const __half* Bp = p.Bp[t];
    const float* bias = p.bias[t];
    const int nodeOff = p.nodeOff[t];
    const int ro0 = p.ro0[t], ro1 = p.ro1[t], ro2 = p.ro2[t];

    const int tid  = threadIdx.x;
    const int lane = tid & 31;
    const int warp = tid >> 5;
    const int wm = (warp & 3) * 32;
    const int wn = (warp >> 2) * 32;

    const int am = tid >> 1;
    const int ak = (tid & 1) * 16;
    const int bk = tid >> 3;
    const int bn = (tid & 7) * 8;

    uint4 pa0, pa1, pb;

    auto load_g = [&](int it) {
        const int seg = it >> segShift;
        const int k0 = (it - (seg << segShift)) * 32;
        const int gm = m0 + am;
        const __half* ap = Aseg[seg] + (size_t)(gm < M ? gm : 0) * aStride + k0 + ak;
        pa0 = *(const uint4*)ap;
        pa1 = *(const uint4*)(ap + 8);
        pb  = *(const uint4*)(Bp + (size_t)(it * 32 + bk) * NPAD + n0 + bn);
    };
    auto store_s = [&]() {
        *(uint4*)&As[am][ak]     = pa0;
        *(uint4*)&As[am][ak + 8] = pa1;
        *(uint4*)&Bs[bk][bn]     = pb;
    };

    float acc[2][4][4];
#pragma unroll
    for (int mi = 0; mi < 2; mi++)
#pragma unroll
        for (int nj = 0; nj < 4; nj++)
#pragma unroll
            for (int r = 0; r < 4; r++) acc[mi][nj][r] = 0.f;

    const uint32_t sA = (uint32_t)__cvta_generic_to_shared(&As[0][0]);
    const uint32_t sB = (uint32_t)__cvta_generic_to_shared(&Bs[0][0]);
    const uint32_t aAddr0 = sA + (uint32_t)((wm + (lane & 15)) * 80 + ((lane >> 4) * 8) * 2);
    const uint32_t bAddr0 = sB + (uint32_t)(((lane & 15)) * 144 + (wn + (lane >> 4) * 8) * 2);

    auto compute = [&]() {
#pragma unroll
        for (int kk = 0; kk < 2; kk++) {
            uint32_t a[2][4], b[4][2];
#pragma unroll
            for (int mi = 0; mi < 2; mi++) {
                uint32_t addr = aAddr0 + (uint32_t)(mi * 16 * 80 + kk * 16 * 2);
                asm volatile("ldmatrix.sync.aligned.m8n8.x4.shared.b16 {%0,%1,%2,%3}, [%4];"
                             : "=r"(a[mi][0]), "=r"(a[mi][1]), "=r"(a[mi][2]), "=r"(a[mi][3])
                             : "r"(addr));
            }
#pragma unroll
            for (int njp = 0; njp < 2; njp++) {
                uint32_t addr = bAddr0 + (uint32_t)(kk * 16 * 144 + njp * 16 * 2);
                asm volatile("ldmatrix.sync.aligned.m8n8.x4.trans.shared.b16 {%0,%1,%2,%3}, [%4];"
                             : "=r"(b[njp * 2][0]), "=r"(b[njp * 2][1]),
                               "=r"(b[njp * 2 + 1][0]), "=r"(b[njp * 2 + 1][1])
                             : "r"(addr));
            }
#pragma unroll
            for (int mi = 0; mi < 2; mi++)
#pragma unroll
                for (int nj = 0; nj < 4; nj++) {
                    asm volatile(
                        "mma.sync.aligned.m16n8k16.row.col.f32.f16.f16.f32 "
                        "{%0,%1,%2,%3}, {%4,%5,%6,%7}, {%8,%9}, {%0,%1,%2,%3};"
                        : "+f"(acc[mi][nj][0]), "+f"(acc[mi][nj][1]),
                          "+f"(acc[mi][nj][2]), "+f"(acc[mi][nj][3])
                        : "r"(a[mi][0]), "r"(a[mi][1]), "r"(a[mi][2]), "r"(a[mi][3]),
                          "r"(b[nj][0]), "r"(b[nj][1]));
                }
        }
    };

    load_g(0);
    store_s();
    __syncthreads();
    for (int it = 1; it < nit; it++) {
        load_g(it);
        compute();
        __syncthreads();
        store_s();
        __syncthreads();
    }
    compute();

    // ---- epilogue ----
#pragma unroll
    for (int mi = 0; mi < 2; mi++)
#pragma unroll
        for (int nj = 0; nj < 4; nj++)
#pragma unroll
            for (int rp = 0; rp < 2; rp++) {
                const int row = m0 + wm + mi * 16 + (lane >> 2) + rp * 8;
                const int col = n0 + wn + nj * 8 + (lane & 3) * 2;
                if (row >= M || col >= Ncols) continue;
                const bool pair = (col + 1 < Ncols);
                const float v0 = acc[mi][nj][rp * 2 + 0] + bias[col];
                const float v1 = acc[mi][nj][rp * 2 + 1] + bias[pair ? col + 1 : col];
                if (mode == 0) {
                    float* pc = p.Cf + (size_t)(nodeOff + row) * 349 + col;
                    pc[0] = v0;
                    if (pair) pc[1] = v1;
                } else {
                    const __half2 h2 = __floats2half2_rn(v0, v1);
                    if (col < 128) {
                        *(__half2*)(g_bases + (size_t)(nodeOff + row) * 128 + col) = h2;
                    } else if (col < 160) {
                        *(__half2*)(g_wroot + (size_t)(nodeOff + row) * 32 + (col - 128)) = h2;
                    } else {
                        const int cc = col - 160;
                        const int rr = cc >> 6;
                        const int ro = (rr == 0) ? ro0 : ((rr == 1) ? ro1 : ro2);
                        *(__half2*)(g_wrel + (size_t)(ro + row) * 64 + (cc & 63)) = h2;
                    }
                }
            }
}

// ---------------------------------------------------------------------------
// merged misc kernel: cvt (fp32->fp16 features) + count (CSR histogram,
// int4-vectorized) + pack_w1 + pack_w2.  All mutually independent.
// block ranges: [0, NB_CVT) cvt | [+NB_CNT) count | [+768) pw1 | [+6144) pw2
// ---------------------------------------------------------------------------
#define NB_CVT 48125           // ceil(49280000/4/256)
#define NB_CNT 2735            // ceil(7*E/4/256)

struct PackT { int R[4], e0[4], e1[4], e2[4]; };

__global__ void __launch_bounds__(256) misc_kernel(
    const float* __restrict__ x0, const float* __restrict__ x1,
    const float* __restrict__ x2, const float* __restrict__ x3,
    const int* __restrict__ dst_idx,
    const float* __restrict__ bases_w1, const float* __restrict__ root_w1,
    const float* __restrict__ rel_w1, const float* __restrict__ root_b1,
    const float* __restrict__ rel_b1, const float* __restrict__ root_w2,
    const float* __restrict__ rel_w2, PackT pt)
{
    const int blk = blockIdx.x;
    const int tid = threadIdx.x;

    if (blk < NB_CVT) {
        // ---- cvt: features -> fp16, float4 per thread ----
        const long long i = ((long long)blk * 256 + tid) * 4;
        if (i >= 49280000LL) return;
        const float* src;
        long long base;
        if (i < 25600000LL)      { src = x0; base = 0; }
        else if (i < 29440000LL) { src = x1; base = 25600000LL; }
        else if (i < 30080000LL) { src = x2; base = 29440000LL; }
        else                     { src = x3; base = 30080000LL; }
        const float4 v = *(const float4*)(src + (i - base));
        union { __half2 h[2]; uint2 u; } pk;
        pk.h[0] = __floats2half2_rn(v.x, v.y);
        pk.h[1] = __floats2half2_rn(v.z, v.w);
        *(uint2*)(g_xh + i) = pk.u;
    } else if (blk < NB_CVT + NB_CNT) {
        // ---- count: 4 edges per thread, int4 (E % 4 == 0 -> same relation) ----
        const long long q4 = ((long long)(blk - NB_CVT) * 256 + tid) * 4;
        if (q4 >= (long long)7 * E) return;
        const int e = (int)(q4 / E);
        const int ro = c_ROFF[e];
        const int4 d = *(const int4*)(dst_idx + q4);
        atomicAdd(&g_cnt[ro + d.x], 1);
        atomicAdd(&g_cnt[ro + d.y], 1);
        atomicAdd(&g_cnt[ro + d.z], 1);
        atomicAdd(&g_cnt[ro + d.w], 1);
    } else if (blk < NB_CVT + NB_CNT + 768) {
        // ---- pack_w1 ----
        const int b = blk - NB_CVT - NB_CNT;
        const int t = b / 192;
        const int i = (b % 192) * 256 + tid;
        const int k = i / NPAD, n = i % NPAD;
        float v = 0.f, bb = 0.f;
        if (n < 128) {
            v = bases_w1[k * 128 + n];
        } else if (n < 160) {
            v = root_w1[((size_t)t * 32 + (n - 128)) * 128 + k];
            bb = root_b1[t * 32 + (n - 128)];
        } else {
            const int cc = n - 160;
            const int r = cc >> 6;
            if (r < pt.R[t]) {
                const int e = (r == 0) ? pt.e0[t] : ((r == 1) ? pt.e1[t] : pt.e2[t]);
                v = rel_w1[((size_t)e * 64 + (cc & 63)) * 128 + k];
                bb = rel_b1[e * 64 + (cc & 63)];
            }
        }
        g_w1p[t][(size_t)k * NPAD + n] = __float2half_rn(v);
        if (k == 0) g_b1p[t][n] = bb;
    } else {
        // ---- pack_w2 ----
        const int b = blk - NB_CVT - NB_CNT - 768;
        const int t = b / 1536;
        const int i = (b % 1536) * 256 + tid;
        const int kg = i / NPAD, n = i % NPAD;
        const int seg = kg >> 8, k = kg & 255;
        if (seg > pt.R[t]) return;
        float v = 0.f;
        if (n < 349) {
            if (seg == 0) v = root_w2[((size_t)t * 349 + n) * 256 + k];
            else {
                const int e = (seg == 1) ? pt.e0[t] : ((seg == 2) ? pt.e1[t] : pt.e2[t]);
                v = rel_w2[((size_t)e * 349 + n) * 256 + k];
            }
        }
        g_w2p[t][(size_t)kg * NPAD + n] = __float2half_rn(v);
    }
}

// ---------------------------------------------------------------------------
// CSR scan + fill (fill int4-vectorized)
// ---------------------------------------------------------------------------
__global__ void __launch_bounds__(256) scan1_kernel()
{
    __shared__ int s[256];
    const int tid = threadIdx.x;
    const int tbase = blockIdx.x * 2048 + tid * 8;
    int vals[8];
    int tsum = 0;
#pragma unroll
    for (int j = 0; j < 8; j++) {
        int v = (tbase + j < RTOT) ? g_cnt[tbase + j] : 0;
        vals[j] = tsum;
        tsum += v;
    }
    s[tid] = tsum;
    __syncthreads();
    for (int off = 1; off < 256; off <<= 1) {
        int t = (tid >= off) ? s[tid - off] : 0;
        __syncthreads();
        s[tid] += t;
        __syncthreads();
    }
    const int texcl = (tid > 0) ? s[tid - 1] : 0;
    if (tid == 255) g_bsum[blockIdx.x] = s[255];
#pragma unroll
    for (int j = 0; j < 8; j++)
        if (tbase + j < RTOT) g_rowptr[tbase + j] = vals[j] + texcl;
}

__global__ void __launch_bounds__(512) scan2_kernel(int nb)
{
    __shared__ int s[512];
    const int tid = threadIdx.x;
    s[tid] = (tid < nb) ? g_bsum[tid] : 0;
    __syncthreads();
    for (int off = 1; off < 512; off <<= 1) {
        int t = (tid >= off) ? s[tid - off] : 0;
        __syncthreads();
        s[tid] += t;
        __syncthreads();
    }
    g_bsum[tid] = (tid > 0) ? s[tid - 1] : 0;
}

__global__ void scan3_kernel()
{
    const int i = blockIdx.x * blockDim.x + threadIdx.x;
    if (i < RTOT) {
        int v = g_rowptr[i] + g_bsum[i >> 11];
        g_rowptr[i] = v;
        g_cursor[i] = v;
    } else if (i == RTOT) {
        g_rowptr[RTOT] = TOTE;
    }
}

__global__ void __launch_bounds__(256) fill_kernel(
    const int* __restrict__ src_idx, const int* __restrict__ dst_idx)
{
    const long long q4 = ((long long)blockIdx.x * 256 + threadIdx.x) * 4;
    if (q4 >= (long long)7 * E) return;
    const int e = (int)(q4 / E);
    const int ro = c_ROFF[e];
    const int so = c_OFF[c_ST[e]];
    const int4 d = *(const int4*)(dst_idx + q4);
    const int4 s = *(const int4*)(src_idx + q4);
    g_ebuf[atomicAdd(&g_cursor[ro + d.x], 1)] = so + s.x;
    g_ebuf[atomicAdd(&g_cursor[ro + d.y], 1)] = so + s.y;
    g_ebuf[atomicAdd(&g_cursor[ro + d.z], 1)] = so + s.z;
    g_ebuf[atomicAdd(&g_cursor[ro + d.w], 1)] = so + s.w;
}

// ---------------------------------------------------------------------------
// L1 fused aggregate+combine — single launch across all types.
// Gather loop 4-way unrolled (sequential adds -> bit-identical).
// ---------------------------------------------------------------------------
struct L1F { int bbase[4], Nn[4], tOff[4], ro0[4], ro1[4], ro2[4], R[4]; };

__global__ void __launch_bounds__(256) l1_fused_all(L1F p)
{
    __shared__ float smb[8][128];
    __shared__ float sma[8][256];

    const int blk = blockIdx.x;
    const int t = (blk >= p.bbase[3]) ? 3 : (blk >= p.bbase[2]) ? 2 :
                  (blk >= p.bbase[1]) ? 1 : 0;
    const int warp = threadIdx.x >> 5;
    const int lane = threadIdx.x & 31;
    const int n = (blk - p.bbase[t]) * 8 + warp;
    if (n >= p.Nn[t]) return;
    const int tOff = p.tOff[t];
    const int R = p.R[t];
    const int c4 = lane * 4;
    const int h  = lane >> 2;

    {
        const uint2 raw = *(const uint2*)(g_bases + (size_t)(tOff + n) * 128 + c4);
        const float2 lo = __half22float2(*(const __half2*)&raw.x);
        const float2 hi = __half22float2(*(const __half2*)&raw.y);
        smb[warp][c4 + 0] = lo.x; smb[warp][c4 + 1] = lo.y;
        smb[warp][c4 + 2] = hi.x; smb[warp][c4 + 3] = hi.y;
    }
    __syncwarp();

    float val[8];
    {
        const uint2 raw = *(const uint2*)(g_wroot + (size_t)(tOff + n) * 32 + h * 4);
        const float2 w01 = __half22float2(*(const __half2*)&raw.x);
        const float2 w23 = __half22float2(*(const __half2*)&raw.y);
#pragma unroll
        for (int j = 0; j < 8; j++) {
            const int dd = (lane * 8 + j) & 31;
            val[j] = w01.x * smb[warp][dd] + w01.y * smb[warp][32 + dd] +
                     w23.x * smb[warp][64 + dd] + w23.y * smb[warp][96 + dd];
        }
    }

    const int roffs[3] = {p.ro0[t], p.ro1[t], p.ro2[t]};
    for (int r = 0; r < R; r++) {
        const int g = roffs[r] + n;
        const int rs = g_rowptr[g];
        const int re = g_rowptr[g + 1];
        const int ct = re - rs;
        float4 s4 = make_float4(0.f, 0.f, 0.f, 0.f);
        float4 m4 = make_float4(-INFINITY, -INFINITY, -INFINITY, -INFINITY);
        int k = rs;
        for (; k + 3 < re; k += 4) {
            const int i0 = g_ebuf[k], i1 = g_ebuf[k + 1];
            const int i2 = g_ebuf[k + 2], i3 = g_ebuf[k + 3];
            const uint2 r0 = *(const uint2*)(g_bases + (size_t)i0 * 128 + c4);
            const uint2 r1 = *(const uint2*)(g_bases + (size_t)i1 * 128 + c4);
            const uint2 r2 = *(const uint2*)(g_bases + (size_t)i2 * 128 + c4);
            const uint2 r3 = *(const uint2*)(g_bases + (size_t)i3 * 128 + c4);
            const uint2 rr[4] = {r0, r1, r2, r3};
#pragma unroll
            for (int u = 0; u < 4; u++) {
                const float2 a0 = __half22float2(*(const __half2*)&rr[u].x);
                const float2 a1 = __half22float2(*(const __half2*)&rr[u].y);
                s4.x += a0.x; s4.y += a0.y; s4.z += a1.x; s4.w += a1.y;
                m4.x = fmaxf(m4.x, a0.x); m4.y = fmaxf(m4.y, a0.y);
                m4.z = fmaxf(m4.z, a1.x); m4.w = fmaxf(m4.w, a1.y);
            }
        }
        for (; k + 1 < re; k += 2) {
            const int i0 = g_ebuf[k], i1 = g_ebuf[k + 1];
            const uint2 r0 = *(const uint2*)(g_bases + (size_t)i0 * 128 + c4);
            const uint2 r1 = *(const uint2*)(g_bases + (size_t)i1 * 128 + c4);
            const uint2 rr[2] = {r0, r1};
#pragma unroll
            for (int u = 0; u < 2; u++) {
                const float2 a0 = __half22float2(*(const __half2*)&rr[u].x);
                const float2 a1 = __half22float2(*(const __half2*)&rr[u].y);
                s4.x += a0.x; s4.y += a0.y; s4.z += a1.x; s4.w += a1.y;
                m4.x = fmaxf(m4.x, a0.x); m4.y = fmaxf(m4.y, a0.y);
                m4.z = fmaxf(m4.z, a1.x); m4.w = fmaxf(m4.w, a1.y);
            }
        }
        if (k < re) {
            const uint2 r0 = *(const uint2*)(g_bases + (size_t)g_ebuf[k] * 128 + c4);
            const float2 a0 = __half22float2(*(const __half2*)&r0.x);
            const float2 a1 = __half22float2(*(const __half2*)&r0.y);
            s4.x += a0.x; s4.y += a0.y; s4.z += a1.x; s4.w += a1.y;
            m4.x = fmaxf(m4.x, a0.x); m4.y = fmaxf(m4.y, a0.y);
            m4.z = fmaxf(m4.z, a1.x); m4.w = fmaxf(m4.w, a1.y);
        }
        const float inv = 1.f / (float)(ct > 1 ? ct : 1);
        s4.x *= inv; s4.y *= inv; s4.z *= inv; s4.w *= inv;
        if (ct == 0) m4 = make_float4(0.f, 0.f, 0.f, 0.f);
        *(float4*)&sma[warp][c4]       = s4;
        *(float4*)&sma[warp][128 + c4] = m4;
        __syncwarp();
        const uint4 raw = *(const uint4*)(g_wrel + (size_t)g * 64 + h * 8);
        const float2 w01 = __half22float2(*(const __half2*)&raw.x);
        const float2 w23 = __half22float2(*(const __half2*)&raw.y);
        const float2 w45 = __half22float2(*(const __half2*)&raw.z);
        const float2 w67 = __half22float2(*(const __half2*)&raw.w);
        const float wv[8] = {w01.x, w01.y, w23.x, w23.y, w45.x, w45.y, w67.x, w67.y};
#pragma unroll
        for (int j = 0; j < 8; j++) {
            const int dd = (lane * 8 + j) & 31;
#pragma unroll
            for (int b = 0; b < 8; b++)
                val[j] += wv[b] * sma[warp][b * 32 + dd];
        }
        __syncwarp();
    }

    union { __half2 h[4]; uint4 u; } pk;
#pragma unroll
    for (int q = 0; q < 4; q++)
        pk.h[q] = __floats2half2_rn(fmaxf(val[2 * q], 0.f), fmaxf(val[2 * q + 1], 0.f));
    *(uint4*)(g_out1 + (size_t)(tOff + n) * 256 + lane * 8) = pk.u;
}

// ---------------------------------------------------------------------------
// L2 aggregation; gather loop 8/4/2/1-way unrolled, sequential adds.
// ---------------------------------------------------------------------------
__global__ void __launch_bounds__(256) l2_agg_kernel()
{
    const int warp = threadIdx.x >> 5;
    const int lane = threadIdx.x & 31;
    const int g = blockIdx.x * 8 + warp;
    if (g >= RTOT) return;
    const int c8 = lane * 8;
    const int rs = g_rowptr[g];
    const int re = g_rowptr[g + 1];
    const int ct = re - rs;
    float a[8];
#pragma unroll
    for (int j = 0; j < 8; j++) a[j] = 0.f;
    int k = rs;
    for (; k + 7 < re; k += 8) {
        int ii[8];
#pragma unroll
        for (int u = 0; u < 8; u++) ii[u] = g_ebuf[k + u];
        uint4 rr[8];
#pragma unroll
        for (int u = 0; u < 8; u++)
            rr[u] = *(const uint4*)(g_out1 + (size_t)ii[u] * 256 + c8);
#pragma unroll
        for (int u = 0; u < 8; u++) {
            const float2 v0 = __half22float2(*(const __half2*)&rr[u].x);
            const float2 v1 = __half22float2(*(const __half2*)&rr[u].y);
            const float2 v2 = __half22float2(*(const __half2*)&rr[u].z);
            const float2 v3 = __half22float2(*(const __half2*)&rr[u].w);
            a[0] += v0.x; a[1] += v0.y; a[2] += v1.x; a[3] += v1.y;
            a[4] += v2.x; a[5] += v2.y; a[6] += v3.x; a[7] += v3.y;
        }
    }
    for (; k + 3 < re; k += 4) {
        int ii[4];
#pragma unroll
        for (int u = 0; u < 4; u++) ii[u] = g_ebuf[k + u];
        uint4 rr[4];
#pragma unroll
        for (int u = 0; u < 4; u++)
            rr[u] = *(const uint4*)(g_out1 + (size_t)ii[u] * 256 + c8);
#pragma unroll
        for (int u = 0; u < 4; u++) {
            const float2 v0 = __half22float2(*(const __half2*)&rr[u].x);
            const float2 v1 = __half22float2(*(const __half2*)&rr[u].y);
            const float2 v2 = __half22float2(*(const __half2*)&rr[u].z);
            const float2 v3 = __half22float2(*(const __half2*)&rr[u].w);
            a[0] += v0.x; a[1] += v0.y; a[2] += v1.x; a[3] += v1.y;
            a[4] += v2.x; a[5] += v2.y; a[6] += v3.x; a[7] += v3.y;
        }
    }
    for (; k + 1 < re; k += 2) {
        const int i0 = g_ebuf[k], i1 = g_ebuf[k + 1];
        const uint4 r0 = *(const uint4*)(g_out1 + (size_t)i0 * 256 + c8);
        const uint4 r1 = *(const uint4*)(g_out1 + (size_t)i1 * 256 + c8);
        const uint4 rr[2] = {r0, r1};
#pragma unroll
        for (int u = 0; u < 2; u++) {
            const float2 v0 = __half22float2(*(const __half2*)&rr[u].x);
            const float2 v1 = __half22float2(*(const __half2*)&rr[u].y);
            const float2 v2 = __half22float2(*(const __half2*)&rr[u].z);
            const float2 v3 = __half22float2(*(const __half2*)&rr[u].w);
            a[0] += v0.x; a[1] += v0.y; a[2] += v1.x; a[3] += v1.y;
            a[4] += v2.x; a[5] += v2.y; a[6] += v3.x; a[7] += v3.y;
        }
    }
    if (k < re) {
        const uint4 r0 = *(const uint4*)(g_out1 + (size_t)g_ebuf[k] * 256 + c8);
        const float2 v0 = __half22float2(*(const __half2*)&r0.x);
        const float2 v1 = __half22float2(*(const __half2*)&r0.y);
        const float2 v2 = __half22float2(*(const __half2*)&r0.z);
        const float2 v3 = __half22float2(*(const __half2*)&r0.w);
        a[0] += v0.x; a[1] += v0.y; a[2] += v1.x; a[3] += v1.y;
        a[4] += v2.x; a[5] += v2.y; a[6] += v3.x; a[7] += v3.y;
    }
    const float inv = 1.f / (float)(ct > 1 ? ct : 1);
    union { __half2 h[4]; uint4 u; } pk;
#pragma unroll
    for (int q = 0; q < 4; q++)
        pk.h[q] = __floats2half2_rn(a[2 * q] * inv, a[2 * q + 1] * inv);
    *(uint4*)(g_sum2 + (size_t)g * 256 + c8) = pk.u;
}

// ---------------------------------------------------------------------------
// host
// ---------------------------------------------------------------------------
extern "C" void kernel_launch(void* const* d_in, const int* in_sizes, int n_in,
                              void* d_out, int out_size)
{
    const float* x_paper    = (const float*)d_in[0];
    const float* emb_author = (const float*)d_in[1];
    const float* emb_fos    = (const float*)d_in[2];
    const float* emb_inst   = (const float*)d_in[3];
    const float* bases_w1   = (const float*)d_in[4];
    const float* rel_w1     = (const float*)d_in[5];
    const float* rel_b1     = (const float*)d_in[6];
    const float* root_w1    = (const float*)d_in[7];
    const float* root_b1    = (const float*)d_in[8];
    const float* rel_w2     = (const float*)d_in[9];
    const float* root_w2    = (const float*)d_in[10];
    const float* root_b2    = (const float*)d_in[11];
    const int*   src_idx    = (const int*)d_in[12];
    const int*   dst_idx    = (const int*)d_in[13];
    float* out = (float*)d_out;

    static const int NUMSh[4] = {200000, 30000, 5000, 150000};
    static const int OFFh[4]  = {0, 200000, 230000, 235000};
    static const int DT[7] = {2, 0, 3, 0, 3, 1, 3};
    static const int ROFFh[7] = {0, 5000, 205000, 355000, 555000, 705000, 735000};

    __half *xh_p, *out1_p, *sum2_p, *w1p_p, *w2p_p;
    float* b1p_p;
    int* cnt_p;
    cudaGetSymbolAddress((void**)&xh_p,    g_xh);
    cudaGetSymbolAddress((void**)&out1_p,  g_out1);
    cudaGetSymbolAddress((void**)&sum2_p,  g_sum2);
    cudaGetSymbolAddress((void**)&w1p_p,   g_w1p);
    cudaGetSymbolAddress((void**)&b1p_p,   g_b1p);
    cudaGetSymbolAddress((void**)&w2p_p,   g_w2p);
    cudaGetSymbolAddress((void**)&cnt_p,   g_cnt);

    int relsOf[4][3], Rof[4];
    for (int t = 0; t < 4; t++) {
        Rof[t] = 0;
        for (int e = 0; e < 7; e++)
            if (DT[e] == t) relsOf[t][Rof[t]++] = e;
        for (int r = Rof[t]; r < 3; r++) relsOf[t][r] = relsOf[t][0];
    }
    PackT pt;
    for (int t = 0; t < 4; t++) {
        pt.R[t] = Rof[t];
        pt.e0[t] = relsOf[t][0]; pt.e1[t] = relsOf[t][1]; pt.e2[t] = relsOf[t][2];
    }

    // ---- merged misc: cvt + count + packs (after cnt memset) ----
    cudaMemsetAsync(cnt_p, 0, (size_t)RTOT * sizeof(int));
    misc_kernel<<<NB_CVT + NB_CNT + 768 + 6144, 256>>>(
        emb_author, emb_fos, emb_inst, x_paper, dst_idx,
        bases_w1, root_w1, rel_w1, root_b1, rel_b1, root_w2, rel_w2, pt);

    // ---- CSR scan + fill ----
    scan1_kernel<<<(RTOT + 2047) / 2048, 256>>>();
    scan2_kernel<<<1, 512>>>((RTOT + 2047) / 2048);
    scan3_kernel<<<(RTOT + 1 + 255) / 256, 256>>>();
    fill_kernel<<<NB_CNT, 256>>>(src_idx, dst_idx);

    // ---- layer-1 merged GEMM (one launch, all types) ----
    {
        GP p;
        p.Cf = out;   // unused in mode 1
        int ms = 0;
        for (int t = 0; t < 4; t++) {
            const __half* A = xh_p + (size_t)OFFh[t] * 128;
            for (int s = 0; s < 4; s++) p.A[t][s] = A;
            p.Bp[t] = w1p_p + (size_t)t * 128 * NPAD;
            p.bias[t] = b1p_p + (size_t)t * NPAD;
            p.mstart[t] = ms;
            ms += (NUMSh[t] + 127) / 128;
            p.M[t] = NUMSh[t];
            p.nodeOff[t] = OFFh[t];
            p.ro0[t] = ROFFh[relsOf[t][0]];
            p.ro1[t] = ROFFh[relsOf[t][1]];
            p.ro2[t] = ROFFh[relsOf[t][2]];
            p.Ncols[t] = 160 + 64 * Rof[t];
            p.nit[t] = 4;
        }
        dim3 grid(6, ms);
        hgemm_multi<<<grid, 256>>>(p, 128, 16, 1);
    }

    // ---- layer-1 fused aggregate+combine (one launch) ----
    {
        L1F p;
        int bb = 0;
        for (int t = 0; t < 4; t++) {
            p.bbase[t] = bb;
            bb += (NUMSh[t] + 7) / 8;
            p.Nn[t] = NUMSh[t];
            p.tOff[t] = OFFh[t];
            p.ro0[t] = ROFFh[relsOf[t][0]];
            p.ro1[t] = ROFFh[relsOf[t][1]];
            p.ro2[t] = ROFFh[relsOf[t][2]];
            p.R[t] = Rof[t];
        }
        l1_fused_all<<<bb, 256>>>(p);
    }

    // ---- layer-2 aggregation ----
    l2_agg_kernel<<<(RTOT + 7) / 8, 256>>>();

    // ---- layer-2 merged multi-segment GEMM (one launch) ----
    {
        GP p;
        p.Cf = out;
        int ms = 0;
        for (int t = 0; t < 4; t++) {
            p.A[t][0] = out1_p + (size_t)OFFh[t] * 256;
            int nseg = 1;
            for (int r = 0; r < Rof[t]; r++)
                p.A[t][nseg++] = sum2_p + (size_t)ROFFh[relsOf[t][r]] * 256;
            for (int s = nseg; s < 4; s++) p.A[t][s] = p.A[t][0];
            p.Bp[t] = w2p_p + (size_t)t * 1024 * NPAD;
            p.bias[t] = root_b2 + (size_t)t * 349;
            p.mstart[t] = ms;
            ms += (NUMSh[t] + 127) / 128;
            p.M[t] = NUMSh[t];
            p.nodeOff[t] = OFFh[t];
            p.ro0[t] = 0; p.ro1[t] = 0; p.ro2[t] = 0;
            p.Ncols[t] = 349;
            p.nit[t] = nseg * 8;
        }
        dim3 grid(6, ms);
        hgemm_multi<<<grid, 256>>>(p, 256, 3, 0);
    }
}